// round 3
// baseline (speedup 1.0000x reference)
#include <cuda_runtime.h>
#include <math.h>

// Problem constants
#define BB  4
#define SS  2048
#define DD  1024
#define HH  16
#define DKK 64
#define MM  (BB*SS)   // 8192 rows

#define PADK 68
#define PADX 36

// Static device scratch
__device__ float    g_Q[(size_t)BB*HH*SS*DKK];   // [B,H,S,DK]
__device__ float    g_K[(size_t)BB*HH*SS*DKK];
__device__ float    g_V[(size_t)BB*HH*SS*DKK];
__device__ float    g_AO[(size_t)BB*SS*DD];      // concat [B,S,D]
__device__ unsigned g_maskbits[SS * (SS/32)];    // bit=1 -> masked

// ---------------------------------------------------------------------------
// helpers
// ---------------------------------------------------------------------------
__device__ __forceinline__ float tf32r(float x) {
    unsigned u;
    asm("cvt.rna.tf32.f32 %0, %1;" : "=r"(u) : "f"(x));
    return __uint_as_float(u);
}
__device__ __forceinline__ float fexp2(float x) {
    float y;
    asm("ex2.approx.ftz.f32 %0, %1;" : "=f"(y) : "f"(x));
    return y;
}
__device__ __forceinline__ void mma8(float* c, float a0, float a1, float a2, float a3,
                                     float b0, float b1) {
    asm volatile(
        "mma.sync.aligned.m16n8k8.row.col.f32.tf32.tf32.f32 "
        "{%0,%1,%2,%3},{%4,%5,%6,%7},{%8,%9},{%0,%1,%2,%3};"
        : "+f"(c[0]), "+f"(c[1]), "+f"(c[2]), "+f"(c[3])
        : "r"(__float_as_uint(a0)), "r"(__float_as_uint(a1)),
          "r"(__float_as_uint(a2)), "r"(__float_as_uint(a3)),
          "r"(__float_as_uint(b0)), "r"(__float_as_uint(b1)));
}

// ---------------------------------------------------------------------------
// mask -> bitmask
// ---------------------------------------------------------------------------
__global__ void mask_bits_kernel(const int* __restrict__ mask) {
    int row  = blockIdx.x;
    int warp = threadIdx.x >> 5;
    int lane = threadIdx.x & 31;
    for (int w = warp; w < SS/32; w += 8) {
        int m = mask[(size_t)row * SS + w*32 + lane];
        unsigned bits = __ballot_sync(0xffffffffu, m == 1);
        if (lane == 0) g_maskbits[row * (SS/32) + w] = bits;
    }
}

// ---------------------------------------------------------------------------
// Fused QKV projection. BM=128, BN=64(=DK), BK=32 per head.
// One X-tile (ctx + val) feeds all three weight MMAs.
// 8 warps: wm 0..3 (32 rows each), wn 0..1 (32 cols each).
// ---------------------------------------------------------------------------
__global__ __launch_bounds__(256)
void qkv_mma_kernel(const float* __restrict__ Xc,
                    const float* __restrict__ Xv,
                    const float* __restrict__ Wq, const float* __restrict__ bq,
                    const float* __restrict__ Wk, const float* __restrict__ bk,
                    const float* __restrict__ Wv, const float* __restrict__ bv)
{
    extern __shared__ float sm[];
    float* Xcs = sm;                    // 128 x 36
    float* Xvs = Xcs + 128*PADX;        // 128 x 36
    float* Wqs = Xvs + 128*PADX;        // 32 x 68
    float* Wks = Wqs + 32*PADK;
    float* Wvs = Wks + 32*PADK;

    const int h    = blockIdx.y;
    const int row0 = blockIdx.x * 128;
    const int tid  = threadIdx.x;
    const int warp = tid >> 5;
    const int lane = tid & 31;
    const int wm   = warp >> 1;
    const int wn   = warp & 1;
    const int lq   = lane >> 2;
    const int lr   = lane & 3;

    const float* Wqh = Wq + (size_t)h * DD * DKK;
    const float* Wkh = Wk + (size_t)h * DD * DKK;
    const float* Wvh = Wv + (size_t)h * DD * DKK;

    float aq[2][4][4], ak[2][4][4], av[2][4][4];
    #pragma unroll
    for (int mt = 0; mt < 2; mt++)
        #pragma unroll
        for (int nt = 0; nt < 4; nt++)
            #pragma unroll
            for (int i = 0; i < 4; i++) {
                aq[mt][nt][i] = 0.0f; ak[mt][nt][i] = 0.0f; av[mt][nt][i] = 0.0f;
            }

    for (int kt = 0; kt < DD; kt += 32) {
        // X tiles 128x32 each
        #pragma unroll
        for (int i = 0; i < 4; i++) {
            int idx = tid + i*256;
            int r = idx >> 3, c4 = idx & 7;
            float4 v = *(const float4*)(Xc + (size_t)(row0 + r)*DD + kt + c4*4);
            v.x = tf32r(v.x); v.y = tf32r(v.y); v.z = tf32r(v.z); v.w = tf32r(v.w);
            *(float4*)&Xcs[r*PADX + c4*4] = v;
            float4 w = *(const float4*)(Xv + (size_t)(row0 + r)*DD + kt + c4*4);
            w.x = tf32r(w.x); w.y = tf32r(w.y); w.z = tf32r(w.z); w.w = tf32r(w.w);
            *(float4*)&Xvs[r*PADX + c4*4] = w;
        }
        // W tiles 32x64 each
        #pragma unroll
        for (int i = 0; i < 2; i++) {
            int idx = tid + i*256;
            int r = idx >> 4, c4 = idx & 15;
            size_t go = (size_t)(kt + r)*DKK + c4*4;
            float4 v = *(const float4*)(Wqh + go);
            v.x = tf32r(v.x); v.y = tf32r(v.y); v.z = tf32r(v.z); v.w = tf32r(v.w);
            *(float4*)&Wqs[r*PADK + c4*4] = v;
            v = *(const float4*)(Wkh + go);
            v.x = tf32r(v.x); v.y = tf32r(v.y); v.z = tf32r(v.z); v.w = tf32r(v.w);
            *(float4*)&Wks[r*PADK + c4*4] = v;
            v = *(const float4*)(Wvh + go);
            v.x = tf32r(v.x); v.y = tf32r(v.y); v.z = tf32r(v.z); v.w = tf32r(v.w);
            *(float4*)&Wvs[r*PADK + c4*4] = v;
        }
        __syncthreads();

        #pragma unroll
        for (int ks = 0; ks < 4; ks++) {
            int kb = ks*8;
            float ac[2][4], axv[2][4];
            #pragma unroll
            for (int mt = 0; mt < 2; mt++) {
                int ar = wm*32 + mt*16 + lq;
                ac[mt][0] = Xcs[ar*PADX + kb + lr];
                ac[mt][1] = Xcs[(ar+8)*PADX + kb + lr];
                ac[mt][2] = Xcs[ar*PADX + kb + 4 + lr];
                ac[mt][3] = Xcs[(ar+8)*PADX + kb + 4 + lr];
                axv[mt][0] = Xvs[ar*PADX + kb + lr];
                axv[mt][1] = Xvs[(ar+8)*PADX + kb + lr];
                axv[mt][2] = Xvs[ar*PADX + kb + 4 + lr];
                axv[mt][3] = Xvs[(ar+8)*PADX + kb + 4 + lr];
            }
            #pragma unroll
            for (int nt = 0; nt < 4; nt++) {
                int bc = wn*32 + nt*8 + lq;
                float q0 = Wqs[(kb + lr)*PADK + bc];
                float q1 = Wqs[(kb + 4 + lr)*PADK + bc];
                float k0 = Wks[(kb + lr)*PADK + bc];
                float k1 = Wks[(kb + 4 + lr)*PADK + bc];
                float v0 = Wvs[(kb + lr)*PADK + bc];
                float v1 = Wvs[(kb + 4 + lr)*PADK + bc];
                #pragma unroll
                for (int mt = 0; mt < 2; mt++) {
                    mma8(aq[mt][nt], ac[mt][0], ac[mt][1], ac[mt][2], ac[mt][3], q0, q1);
                    mma8(ak[mt][nt], ac[mt][0], ac[mt][1], ac[mt][2], ac[mt][3], k0, k1);
                    mma8(av[mt][nt], axv[mt][0], axv[mt][1], axv[mt][2], axv[mt][3], v0, v1);
                }
            }
        }
        __syncthreads();
    }

    // epilogue: 3 outputs
    #pragma unroll
    for (int nt = 0; nt < 4; nt++) {
        int col = wn*32 + nt*8 + 2*lr;
        float bq0 = bq[h*DKK + col], bq1 = bq[h*DKK + col + 1];
        float bk0 = bk[h*DKK + col], bk1 = bk[h*DKK + col + 1];
        float bv0 = bv[h*DKK + col], bv1 = bv[h*DKK + col + 1];
        #pragma unroll
        for (int mt = 0; mt < 2; mt++) {
            #pragma unroll
            for (int half = 0; half < 2; half++) {
                int grow = row0 + wm*32 + mt*16 + lq + half*8;
                int b = grow / SS, s = grow % SS;
                size_t o = ((size_t)(b*HH + h)*SS + s)*DKK + col;
                float2 v;
                v.x = aq[mt][nt][half*2+0] + bq0; v.y = aq[mt][nt][half*2+1] + bq1;
                *(float2*)(g_Q + o) = v;
                v.x = ak[mt][nt][half*2+0] + bk0; v.y = ak[mt][nt][half*2+1] + bk1;
                *(float2*)(g_K + o) = v;
                v.x = av[mt][nt][half*2+0] + bv0; v.y = av[mt][nt][half*2+1] + bv1;
                *(float2*)(g_V + o) = v;
            }
        }
    }
}

// ---------------------------------------------------------------------------
// Flash attention, BR=128, BC=64. Q fragments live in registers.
// ---------------------------------------------------------------------------
__global__ __launch_bounds__(256, 2)
void attn_mma_kernel()
{
    extern __shared__ float sm[];
    float* Ks = sm;                    // 64 x 68
    float* Vs = Ks + 64*PADK;          // 64 x 68
    float* Ps = Vs + 64*PADK;          // 128 x 68

    const int bh  = blockIdx.y;
    const int qr0 = blockIdx.x * 128;
    const int tid = threadIdx.x;
    const int wm  = tid >> 5;
    const int lane= tid & 31;
    const int lq  = lane >> 2;
    const int lr  = lane & 3;

    const float* Qg = g_Q + (size_t)bh * SS * DKK;
    const float* Kg = g_K + (size_t)bh * SS * DKK;
    const float* Vg = g_V + (size_t)bh * SS * DKK;

    const int lrow  = wm*16 + lq;
    const int grow0 = qr0 + lrow;
    const int grow1 = grow0 + 8;

    // Q fragments -> registers (tf32-rounded), cover full DK=64
    float q[8][4];
    #pragma unroll
    for (int ks = 0; ks < 8; ks++) {
        q[ks][0] = tf32r(Qg[(size_t)grow0*DKK + ks*8 + lr]);
        q[ks][1] = tf32r(Qg[(size_t)grow1*DKK + ks*8 + lr]);
        q[ks][2] = tf32r(Qg[(size_t)grow0*DKK + ks*8 + 4 + lr]);
        q[ks][3] = tf32r(Qg[(size_t)grow1*DKK + ks*8 + 4 + lr]);
    }

    float o[8][4];
    float m0 = -1e30f, m1 = -1e30f, l0 = 0.0f, l1 = 0.0f;
    #pragma unroll
    for (int nt = 0; nt < 8; nt++)
        #pragma unroll
        for (int i = 0; i < 4; i++) o[nt][i] = 0.0f;

    const float SCL = 0.18033688011112042f;   // 0.125 * log2(e)

    for (int kt0 = 0; kt0 < SS; kt0 += 64) {
        __syncthreads();
        #pragma unroll
        for (int i = 0; i < 4; i++) {
            int idx = tid + i*256;
            int r = idx >> 4, c4 = idx & 15;
            float4 kv = *(const float4*)(Kg + (size_t)(kt0 + r)*DKK + c4*4);
            kv.x = tf32r(kv.x); kv.y = tf32r(kv.y); kv.z = tf32r(kv.z); kv.w = tf32r(kv.w);
            *(float4*)&Ks[r*PADK + c4*4] = kv;
            float4 vv = *(const float4*)(Vg + (size_t)(kt0 + r)*DKK + c4*4);
            vv.x = tf32r(vv.x); vv.y = tf32r(vv.y); vv.z = tf32r(vv.z); vv.w = tf32r(vv.w);
            *(float4*)&Vs[r*PADK + c4*4] = vv;
        }
        __syncthreads();

        // S = Q . K^T
        float s[8][4];
        #pragma unroll
        for (int nt = 0; nt < 8; nt++)
            #pragma unroll
            for (int i = 0; i < 4; i++) s[nt][i] = 0.0f;

        #pragma unroll
        for (int ks = 0; ks < 8; ks++) {
            int kb = ks*8;
            #pragma unroll
            for (int nt = 0; nt < 8; nt++) {
                int bc = nt*8 + lq;
                float b0 = Ks[bc*PADK + kb + lr];
                float b1 = Ks[bc*PADK + kb + 4 + lr];
                mma8(s[nt], q[ks][0], q[ks][1], q[ks][2], q[ks][3], b0, b1);
            }
        }

        // mask + scale
        unsigned w0a = g_maskbits[grow0*(SS/32) + (kt0>>5)];
        unsigned w0b = g_maskbits[grow0*(SS/32) + (kt0>>5) + 1];
        unsigned w1a = g_maskbits[grow1*(SS/32) + (kt0>>5)];
        unsigned w1b = g_maskbits[grow1*(SS/32) + (kt0>>5) + 1];
        #pragma unroll
        for (int nt = 0; nt < 8; nt++) {
            int c = nt*8 + 2*lr;
            unsigned wr0 = (c < 32) ? w0a : w0b;
            unsigned wr1 = (c < 32) ? w1a : w1b;
            int sh = c & 31;
            s[nt][0] = ((wr0 >> sh)     & 1u) ? -1e9f : s[nt][0]*SCL;
            s[nt][1] = ((wr0 >> (sh+1)) & 1u) ? -1e9f : s[nt][1]*SCL;
            s[nt][2] = ((wr1 >> sh)     & 1u) ? -1e9f : s[nt][2]*SCL;
            s[nt][3] = ((wr1 >> (sh+1)) & 1u) ? -1e9f : s[nt][3]*SCL;
        }

        // online softmax, base-2 domain
        float mx0 = -1e30f, mx1 = -1e30f;
        #pragma unroll
        for (int nt = 0; nt < 8; nt++) {
            mx0 = fmaxf(mx0, fmaxf(s[nt][0], s[nt][1]));
            mx1 = fmaxf(mx1, fmaxf(s[nt][2], s[nt][3]));
        }
        mx0 = fmaxf(mx0, __shfl_xor_sync(0xffffffffu, mx0, 1));
        mx0 = fmaxf(mx0, __shfl_xor_sync(0xffffffffu, mx0, 2));
        mx1 = fmaxf(mx1, __shfl_xor_sync(0xffffffffu, mx1, 1));
        mx1 = fmaxf(mx1, __shfl_xor_sync(0xffffffffu, mx1, 2));
        float mn0 = fmaxf(m0, mx0);
        float mn1 = fmaxf(m1, mx1);
        float sum0 = 0.0f, sum1 = 0.0f;
        #pragma unroll
        for (int nt = 0; nt < 8; nt++) {
            s[nt][0] = fexp2(s[nt][0] - mn0); sum0 += s[nt][0];
            s[nt][1] = fexp2(s[nt][1] - mn0); sum0 += s[nt][1];
            s[nt][2] = fexp2(s[nt][2] - mn1); sum1 += s[nt][2];
            s[nt][3] = fexp2(s[nt][3] - mn1); sum1 += s[nt][3];
        }
        sum0 += __shfl_xor_sync(0xffffffffu, sum0, 1);
        sum0 += __shfl_xor_sync(0xffffffffu, sum0, 2);
        sum1 += __shfl_xor_sync(0xffffffffu, sum1, 1);
        sum1 += __shfl_xor_sync(0xffffffffu, sum1, 2);
        float sc0 = fexp2(m0 - mn0);
        float sc1 = fexp2(m1 - mn1);
        l0 = l0*sc0 + sum0;  m0 = mn0;
        l1 = l1*sc1 + sum1;  m1 = mn1;
        #pragma unroll
        for (int nt = 0; nt < 8; nt++) {
            o[nt][0] *= sc0; o[nt][1] *= sc0;
            o[nt][2] *= sc1; o[nt][3] *= sc1;
        }

        // P -> smem (warp-private rows; tf32-rounded)
        #pragma unroll
        for (int nt = 0; nt < 8; nt++) {
            int c = nt*8 + 2*lr;
            float2 p0; p0.x = tf32r(s[nt][0]); p0.y = tf32r(s[nt][1]);
            float2 p1; p1.x = tf32r(s[nt][2]); p1.y = tf32r(s[nt][3]);
            *(float2*)&Ps[lrow*PADK + c]     = p0;
            *(float2*)&Ps[(lrow+8)*PADK + c] = p1;
        }
        __syncwarp();

        // O += P . V
        #pragma unroll
        for (int ks = 0; ks < 8; ks++) {
            int kb = ks*8;
            float a0 = Ps[lrow*PADK + kb + lr];
            float a1 = Ps[(lrow+8)*PADK + kb + lr];
            float a2 = Ps[lrow*PADK + kb + 4 + lr];
            float a3 = Ps[(lrow+8)*PADK + kb + 4 + lr];
            #pragma unroll
            for (int nt = 0; nt < 8; nt++) {
                int bc = nt*8 + lq;
                float b0 = Vs[(kb + lr)*PADK + bc];
                float b1 = Vs[(kb + 4 + lr)*PADK + bc];
                mma8(o[nt], a0, a1, a2, a3, b0, b1);
            }
        }
        __syncwarp();
    }

    // epilogue -> concat layout
    const int b = bh >> 4, h = bh & 15;
    float inv0 = 1.0f / l0, inv1 = 1.0f / l1;
    #pragma unroll
    for (int nt = 0; nt < 8; nt++) {
        int c = nt*8 + 2*lr;
        size_t base0 = ((size_t)(b*SS + grow0))*DD + h*DKK + c;
        size_t base1 = ((size_t)(b*SS + grow1))*DD + h*DKK + c;
        float2 v0; v0.x = o[nt][0]*inv0; v0.y = o[nt][1]*inv0;
        float2 v1; v1.x = o[nt][2]*inv1; v1.y = o[nt][3]*inv1;
        *(float2*)(g_AO + base0) = v0;
        *(float2*)(g_AO + base1) = v1;
    }
}

// ---------------------------------------------------------------------------
// Output projection (NT): out[m,n] = AO[m,:] . Wo[n,:] + bo[n]
// ---------------------------------------------------------------------------
__global__ __launch_bounds__(256)
void outproj_mma_kernel(const float* __restrict__ Wo,
                        const float* __restrict__ bo,
                        float* __restrict__ out)
{
    __shared__ float As[128*36];
    __shared__ float Ws[64*36];

    const int n0   = blockIdx.x * 64;
    const int row0 = blockIdx.y * 128;
    const int tid  = threadIdx.x;
    const int warp = tid >> 5;
    const int lane = tid & 31;
    const int wm   = warp >> 1;
    const int wn   = warp & 1;
    const int lq   = lane >> 2;
    const int lr   = lane & 3;

    float acc[2][4][4];
    #pragma unroll
    for (int mt = 0; mt < 2; mt++)
        #pragma unroll
        for (int nt = 0; nt < 4; nt++)
            #pragma unroll
            for (int i = 0; i < 4; i++) acc[mt][nt][i] = 0.0f;

    for (int kt = 0; kt < DD; kt += 32) {
        #pragma unroll
        for (int i = 0; i < 4; i++) {
            int idx = tid + i*256;
            int r = idx >> 3, c4 = idx & 7;
            float4 v = *(const float4*)(g_AO + (size_t)(row0 + r)*DD + kt + c4*4);
            v.x = tf32r(v.x); v.y = tf32r(v.y); v.z = tf32r(v.z); v.w = tf32r(v.w);
            *(float4*)&As[r*36 + c4*4] = v;
        }
        #pragma unroll
        for (int i = 0; i < 2; i++) {
            int idx = tid + i*256;
            int r = idx >> 3, c4 = idx & 7;
            float4 v = *(const float4*)(Wo + (size_t)(n0 + r)*DD + kt + c4*4);
            v.x = tf32r(v.x); v.y = tf32r(v.y); v.z = tf32r(v.z); v.w = tf32r(v.w);
            *(float4*)&Ws[r*36 + c4*4] = v;
        }
        __syncthreads();

        #pragma unroll
        for (int ks = 0; ks < 4; ks++) {
            int kb = ks*8;
            float a[2][4];
            #pragma unroll
            for (int mt = 0; mt < 2; mt++) {
                int ar = wm*32 + mt*16 + lq;
                a[mt][0] = As[ar*36 + kb + lr];
                a[mt][1] = As[(ar+8)*36 + kb + lr];
                a[mt][2] = As[ar*36 + kb + 4 + lr];
                a[mt][3] = As[(ar+8)*36 + kb + 4 + lr];
            }
            #pragma unroll
            for (int nt = 0; nt < 4; nt++) {
                int nc = wn*32 + nt*8 + lq;
                float b0 = Ws[nc*36 + kb + lr];
                float b1 = Ws[nc*36 + kb + 4 + lr];
                #pragma unroll
                for (int mt = 0; mt < 2; mt++)
                    mma8(acc[mt][nt], a[mt][0], a[mt][1], a[mt][2], a[mt][3], b0, b1);
            }
        }
        __syncthreads();
    }

    #pragma unroll
    for (int nt = 0; nt < 4; nt++) {
        int col = n0 + wn*32 + nt*8 + 2*lr;
        float bv0 = bo[col], bv1 = bo[col+1];
        #pragma unroll
        for (int mt = 0; mt < 2; mt++) {
            #pragma unroll
            for (int half = 0; half < 2; half++) {
                size_t grow = row0 + wm*32 + mt*16 + lq + half*8;
                float2 v;
                v.x = acc[mt][nt][half*2+0] + bv0;
                v.y = acc[mt][nt][half*2+1] + bv1;
                *(float2*)(out + grow*DD + col) = v;
            }
        }
    }
}

// ---------------------------------------------------------------------------
extern "C" void kernel_launch(void* const* d_in, const int* in_sizes, int n_in,
                              void* d_out, int out_size)
{
    const float* ctx  = (const float*)d_in[0];
    const float* val  = (const float*)d_in[1];
    const int*   mask = (const int*)  d_in[2];
    const float* Wq   = (const float*)d_in[3];
    const float* bq   = (const float*)d_in[4];
    const float* Wk   = (const float*)d_in[5];
    const float* bk   = (const float*)d_in[6];
    const float* Wv   = (const float*)d_in[7];
    const float* bv   = (const float*)d_in[8];
    const float* Wo   = (const float*)d_in[9];
    const float* bo   = (const float*)d_in[10];
    float* out = (float*)d_out;
    (void)in_sizes; (void)n_in; (void)out_size;

    // mask -> bits
    mask_bits_kernel<<<SS, 256>>>(mask);

    // fused QKV projection
    int qkv_smem = (2*128*PADX + 3*32*PADK) * (int)sizeof(float);  // 62976
    cudaFuncSetAttribute(qkv_mma_kernel, cudaFuncAttributeMaxDynamicSharedMemorySize, qkv_smem);
    dim3 pgrid(MM / 128, HH);
    qkv_mma_kernel<<<pgrid, 256, qkv_smem>>>(ctx, val, Wq, bq, Wk, bk, Wv, bv);

    // attention
    int attn_smem = (64 + 64 + 128) * PADK * (int)sizeof(float);   // 69632
    cudaFuncSetAttribute(attn_mma_kernel, cudaFuncAttributeMaxDynamicSharedMemorySize, attn_smem);
    dim3 agrid(SS / 128, BB * HH);
    attn_mma_kernel<<<agrid, 256, attn_smem>>>();

    // output projection
    dim3 ogrid(DD / 64, MM / 128);
    outproj_mma_kernel<<<ogrid, 256>>>(Wo, bo, out);
}

// round 5
// speedup vs baseline: 1.2452x; 1.2452x over previous
#include <cuda_runtime.h>
#include <cstdint>
#include <math.h>

// Problem constants
#define BB  4
#define SS  2048
#define DD  1024
#define HH  16
#define DKK 64
#define MM  (BB*SS)

#define PADK 68
#define PADX 36

// Static device scratch
__device__ float    g_Q[(size_t)BB*HH*SS*DKK];   // [B,H,S,DK], tf32-rounded
__device__ float    g_K[(size_t)BB*HH*SS*DKK];   // tf32-rounded
__device__ float    g_V[(size_t)BB*HH*SS*DKK];   // tf32-rounded
__device__ float    g_AO[(size_t)BB*SS*DD];      // concat [B,S,D], f32
__device__ unsigned g_maskbits[SS * (SS/32)];

// ---------------------------------------------------------------------------
__device__ __forceinline__ float tf32r(float x) {
    unsigned int u;
    asm("cvt.rna.tf32.f32 %0, %1;" : "=r"(u) : "f"(x));
    return __uint_as_float(u);
}
__device__ __forceinline__ float fexp2(float x) {
    float y;
    asm("ex2.approx.ftz.f32 %0, %1;" : "=f"(y) : "f"(x));
    return y;
}
__device__ __forceinline__ void mma8(float* c, float a0, float a1, float a2, float a3,
                                     float b0, float b1) {
    asm volatile(
        "mma.sync.aligned.m16n8k8.row.col.f32.tf32.tf32.f32 "
        "{%0,%1,%2,%3},{%4,%5,%6,%7},{%8,%9},{%0,%1,%2,%3};"
        : "+f"(c[0]), "+f"(c[1]), "+f"(c[2]), "+f"(c[3])
        : "r"(__float_as_uint(a0)), "r"(__float_as_uint(a1)),
          "r"(__float_as_uint(a2)), "r"(__float_as_uint(a3)),
          "r"(__float_as_uint(b0)), "r"(__float_as_uint(b1)));
}
__device__ __forceinline__ void cp16(unsigned int dst, const float* src) {
    asm volatile("cp.async.cg.shared.global [%0], [%1], 16;" :: "r"(dst), "l"(src));
}
__device__ __forceinline__ void cp_commit() {
    asm volatile("cp.async.commit_group;");
}
__device__ __forceinline__ void cp_wait1() {
    asm volatile("cp.async.wait_group 1;");
}

// ---------------------------------------------------------------------------
__global__ void mask_bits_kernel(const int* __restrict__ mask) {
    int row  = blockIdx.x;
    int warp = threadIdx.x >> 5;
    int lane = threadIdx.x & 31;
    for (int w = warp; w < SS/32; w += 8) {
        int m = mask[(size_t)row * SS + w*32 + lane];
        unsigned bits = __ballot_sync(0xffffffffu, m == 1);
        if (lane == 0) g_maskbits[row * (SS/32) + w] = bits;
    }
}

// ---------------------------------------------------------------------------
// Projection, 2 heads per CTA. BM=128, BN=64 per head, BK=32.
// WHICH: 0->g_Q, 1->g_K, 2->g_V. Outputs stored tf32-rounded.
// ---------------------------------------------------------------------------
template<int WHICH>
__global__ __launch_bounds__(256)
void proj2_mma_kernel(const float* __restrict__ X,
                      const float* __restrict__ W,
                      const float* __restrict__ bias)
{
    __shared__ float Xs[128*PADX];
    __shared__ float Ws[2][32*PADK];

    float* out = (WHICH == 0) ? g_Q : (WHICH == 1) ? g_K : g_V;

    const int h0   = blockIdx.y * 2;
    const int row0 = blockIdx.x * 128;
    const int tid  = threadIdx.x;
    const int warp = tid >> 5;
    const int lane = tid & 31;
    const int wm   = warp >> 1;
    const int wn   = warp & 1;
    const int lq   = lane >> 2;
    const int lr   = lane & 3;

    float acc[2][2][4][4];   // [head][mt][nt][4]
    #pragma unroll
    for (int hh = 0; hh < 2; hh++)
        #pragma unroll
        for (int mt = 0; mt < 2; mt++)
            #pragma unroll
            for (int nt = 0; nt < 4; nt++)
                #pragma unroll
                for (int i = 0; i < 4; i++) acc[hh][mt][nt][i] = 0.0f;

    for (int kt = 0; kt < DD; kt += 32) {
        #pragma unroll
        for (int i = 0; i < 4; i++) {
            int idx = tid + i*256;
            int r = idx >> 3, c4 = idx & 7;
            float4 v = *(const float4*)(X + (size_t)(row0 + r)*DD + kt + c4*4);
            v.x = tf32r(v.x); v.y = tf32r(v.y); v.z = tf32r(v.z); v.w = tf32r(v.w);
            *(float4*)&Xs[r*PADX + c4*4] = v;
        }
        #pragma unroll
        for (int hh = 0; hh < 2; hh++) {
            const float* Wh = W + (size_t)(h0 + hh) * DD * DKK;
            #pragma unroll
            for (int i = 0; i < 2; i++) {
                int idx = tid + i*256;
                int r = idx >> 4, c4 = idx & 15;
                float4 v = *(const float4*)(Wh + (size_t)(kt + r)*DKK + c4*4);
                v.x = tf32r(v.x); v.y = tf32r(v.y); v.z = tf32r(v.z); v.w = tf32r(v.w);
                *(float4*)&Ws[hh][r*PADK + c4*4] = v;
            }
        }
        __syncthreads();

        #pragma unroll
        for (int ks = 0; ks < 4; ks++) {
            int kb = ks*8;
            float a[2][4];
            #pragma unroll
            for (int mt = 0; mt < 2; mt++) {
                int ar = wm*32 + mt*16 + lq;
                a[mt][0] = Xs[ar*PADX + kb + lr];
                a[mt][1] = Xs[(ar+8)*PADX + kb + lr];
                a[mt][2] = Xs[ar*PADX + kb + 4 + lr];
                a[mt][3] = Xs[(ar+8)*PADX + kb + 4 + lr];
            }
            #pragma unroll
            for (int hh = 0; hh < 2; hh++) {
                #pragma unroll
                for (int nt = 0; nt < 4; nt++) {
                    int bc = wn*32 + nt*8 + lq;
                    float b0 = Ws[hh][(kb + lr)*PADK + bc];
                    float b1 = Ws[hh][(kb + 4 + lr)*PADK + bc];
                    #pragma unroll
                    for (int mt = 0; mt < 2; mt++)
                        mma8(acc[hh][mt][nt], a[mt][0], a[mt][1], a[mt][2], a[mt][3], b0, b1);
                }
            }
        }
        __syncthreads();
    }

    // epilogue: tf32-rounded store
    #pragma unroll
    for (int hh = 0; hh < 2; hh++) {
        int h = h0 + hh;
        #pragma unroll
        for (int nt = 0; nt < 4; nt++) {
            int col = wn*32 + nt*8 + 2*lr;
            float bv0 = bias[h*DKK + col], bv1 = bias[h*DKK + col + 1];
            #pragma unroll
            for (int mt = 0; mt < 2; mt++) {
                #pragma unroll
                for (int half = 0; half < 2; half++) {
                    int grow = row0 + wm*32 + mt*16 + lq + half*8;
                    int b = grow / SS, s = grow % SS;
                    size_t o = ((size_t)(b*HH + h)*SS + s)*DKK + col;
                    float2 v;
                    v.x = tf32r(acc[hh][mt][nt][half*2+0] + bv0);
                    v.y = tf32r(acc[hh][mt][nt][half*2+1] + bv1);
                    *(float2*)(out + o) = v;
                }
            }
        }
    }
}

// ---------------------------------------------------------------------------
// Flash attention, BR=128, BC=64. Q in registers (pre-rounded tf32 in gmem).
// K/V tiles streamed via cp.async double buffering.
// smem: KV[2][K 64x68 + V 64x68] + Ps[128x68] = 104448 bytes.
// ---------------------------------------------------------------------------
__global__ __launch_bounds__(256)
void attn_mma_kernel()
{
    extern __shared__ float sm[];
    float* KV = sm;                     // 2 bufs x (64*68 K + 64*68 V)
    float* Ps = KV + 4*64*PADK;         // 128 x 68

    const int bh  = blockIdx.y;
    const int qr0 = blockIdx.x * 128;
    const int tid = threadIdx.x;
    const int wm  = tid >> 5;
    const int lane= tid & 31;
    const int lq  = lane >> 2;
    const int lr  = lane & 3;

    const float* Qg = g_Q + (size_t)bh * SS * DKK;
    const float* Kg = g_K + (size_t)bh * SS * DKK;
    const float* Vg = g_V + (size_t)bh * SS * DKK;

    const int lrow  = wm*16 + lq;
    const int grow0 = qr0 + lrow;
    const int grow1 = grow0 + 8;

    // per-thread cp.async indexing (4 chunks K + 4 chunks V)
    const int cr  = tid >> 4;            // 0..15 base row
    const int cc4 = tid & 15;            // 0..15 chunk col
    const unsigned int kv_s = (unsigned int)__cvta_generic_to_shared(KV);

    // prologue: issue tile 0 into buf 0
    {
        unsigned int kd = kv_s + (unsigned int)(cr*PADK + cc4*4) * 4u;
        unsigned int vd = kd + (unsigned int)(64*PADK*4);
        #pragma unroll
        for (int i = 0; i < 4; i++) {
            int r = cr + i*16;
            cp16(kd + (unsigned int)(i*16*PADK*4), Kg + (size_t)r*DKK + cc4*4);
            cp16(vd + (unsigned int)(i*16*PADK*4), Vg + (size_t)r*DKK + cc4*4);
        }
        cp_commit();
    }

    // Q fragments -> registers (already tf32)
    float q[8][4];
    #pragma unroll
    for (int ks = 0; ks < 8; ks++) {
        q[ks][0] = Qg[(size_t)grow0*DKK + ks*8 + lr];
        q[ks][1] = Qg[(size_t)grow1*DKK + ks*8 + lr];
        q[ks][2] = Qg[(size_t)grow0*DKK + ks*8 + 4 + lr];
        q[ks][3] = Qg[(size_t)grow1*DKK + ks*8 + 4 + lr];
    }

    float o[8][4];
    float m0 = -1e30f, m1 = -1e30f, l0 = 0.0f, l1 = 0.0f;
    #pragma unroll
    for (int nt = 0; nt < 8; nt++)
        #pragma unroll
        for (int i = 0; i < 4; i++) o[nt][i] = 0.0f;

    const float SCL = 0.18033688011112042f;   // 0.125 * log2(e)

    for (int it = 0; it < SS/64; it++) {
        int buf = it & 1;
        float* Ks = KV + buf*2*64*PADK;
        float* Vs = Ks + 64*PADK;

        // prefetch tile it+1 into buf^1
        if (it + 1 < SS/64) {
            int kt1 = (it + 1) * 64;
            unsigned int kd = kv_s + (unsigned int)((buf^1)*2*64*PADK + cr*PADK + cc4*4) * 4u;
            unsigned int vd = kd + (unsigned int)(64*PADK*4);
            #pragma unroll
            for (int i = 0; i < 4; i++) {
                int r = kt1 + cr + i*16;
                cp16(kd + (unsigned int)(i*16*PADK*4), Kg + (size_t)r*DKK + cc4*4);
                cp16(vd + (unsigned int)(i*16*PADK*4), Vg + (size_t)r*DKK + cc4*4);
            }
        }
        cp_commit();
        cp_wait1();          // tile `it` complete (all but newest group)
        __syncthreads();     // make copies visible to all warps

        // S = Q . K^T
        float s[8][4];
        #pragma unroll
        for (int nt = 0; nt < 8; nt++)
            #pragma unroll
            for (int i = 0; i < 4; i++) s[nt][i] = 0.0f;

        #pragma unroll
        for (int ks = 0; ks < 8; ks++) {
            int kb = ks*8;
            #pragma unroll
            for (int nt = 0; nt < 8; nt++) {
                int bc = nt*8 + lq;
                float b0 = Ks[bc*PADK + kb + lr];
                float b1 = Ks[bc*PADK + kb + 4 + lr];
                mma8(s[nt], q[ks][0], q[ks][1], q[ks][2], q[ks][3], b0, b1);
            }
        }

        // mask + scale
        int kt0 = it * 64;
        unsigned w0a = g_maskbits[grow0*(SS/32) + (kt0>>5)];
        unsigned w0b = g_maskbits[grow0*(SS/32) + (kt0>>5) + 1];
        unsigned w1a = g_maskbits[grow1*(SS/32) + (kt0>>5)];
        unsigned w1b = g_maskbits[grow1*(SS/32) + (kt0>>5) + 1];
        #pragma unroll
        for (int nt = 0; nt < 8; nt++) {
            int c = nt*8 + 2*lr;
            unsigned wr0 = (c < 32) ? w0a : w0b;
            unsigned wr1 = (c < 32) ? w1a : w1b;
            int sh = c & 31;
            s[nt][0] = ((wr0 >> sh)     & 1u) ? -1e9f : s[nt][0]*SCL;
            s[nt][1] = ((wr0 >> (sh+1)) & 1u) ? -1e9f : s[nt][1]*SCL;
            s[nt][2] = ((wr1 >> sh)     & 1u) ? -1e9f : s[nt][2]*SCL;
            s[nt][3] = ((wr1 >> (sh+1)) & 1u) ? -1e9f : s[nt][3]*SCL;
        }

        // online softmax (base-2)
        float mx0 = -1e30f, mx1 = -1e30f;
        #pragma unroll
        for (int nt = 0; nt < 8; nt++) {
            mx0 = fmaxf(mx0, fmaxf(s[nt][0], s[nt][1]));
            mx1 = fmaxf(mx1, fmaxf(s[nt][2], s[nt][3]));
        }
        mx0 = fmaxf(mx0, __shfl_xor_sync(0xffffffffu, mx0, 1));
        mx0 = fmaxf(mx0, __shfl_xor_sync(0xffffffffu, mx0, 2));
        mx1 = fmaxf(mx1, __shfl_xor_sync(0xffffffffu, mx1, 1));
        mx1 = fmaxf(mx1, __shfl_xor_sync(0xffffffffu, mx1, 2));
        float mn0 = fmaxf(m0, mx0);
        float mn1 = fmaxf(m1, mx1);
        float sum0 = 0.0f, sum1 = 0.0f;
        #pragma unroll
        for (int nt = 0; nt < 8; nt++) {
            s[nt][0] = fexp2(s[nt][0] - mn0); sum0 += s[nt][0];
            s[nt][1] = fexp2(s[nt][1] - mn0); sum0 += s[nt][1];
            s[nt][2] = fexp2(s[nt][2] - mn1); sum1 += s[nt][2];
            s[nt][3] = fexp2(s[nt][3] - mn1); sum1 += s[nt][3];
        }
        sum0 += __shfl_xor_sync(0xffffffffu, sum0, 1);
        sum0 += __shfl_xor_sync(0xffffffffu, sum0, 2);
        sum1 += __shfl_xor_sync(0xffffffffu, sum1, 1);
        sum1 += __shfl_xor_sync(0xffffffffu, sum1, 2);
        float sc0 = fexp2(m0 - mn0);
        float sc1 = fexp2(m1 - mn1);
        l0 = l0*sc0 + sum0;  m0 = mn0;
        l1 = l1*sc1 + sum1;  m1 = mn1;
        #pragma unroll
        for (int nt = 0; nt < 8; nt++) {
            o[nt][0] *= sc0; o[nt][1] *= sc0;
            o[nt][2] *= sc1; o[nt][3] *= sc1;
        }

        // P -> smem (warp-private rows)
        #pragma unroll
        for (int nt = 0; nt < 8; nt++) {
            int c = nt*8 + 2*lr;
            float2 p0; p0.x = tf32r(s[nt][0]); p0.y = tf32r(s[nt][1]);
            float2 p1; p1.x = tf32r(s[nt][2]); p1.y = tf32r(s[nt][3]);
            *(float2*)&Ps[lrow*PADK + c]     = p0;
            *(float2*)&Ps[(lrow+8)*PADK + c] = p1;
        }
        __syncwarp();

        // O += P . V
        #pragma unroll
        for (int ks = 0; ks < 8; ks++) {
            int kb = ks*8;
            float a0 = Ps[lrow*PADK + kb + lr];
            float a1 = Ps[(lrow+8)*PADK + kb + lr];
            float a2 = Ps[lrow*PADK + kb + 4 + lr];
            float a3 = Ps[(lrow+8)*PADK + kb + 4 + lr];
            #pragma unroll
            for (int nt = 0; nt < 8; nt++) {
                int bc = nt*8 + lq;
                float b0 = Vs[(kb + lr)*PADK + bc];
                float b1 = Vs[(kb + 4 + lr)*PADK + bc];
                mma8(o[nt], a0, a1, a2, a3, b0, b1);
            }
        }
        __syncthreads();   // all warps done with this buf before refill
    }

    // epilogue -> concat layout
    const int b = bh >> 4, h = bh & 15;
    float inv0 = 1.0f / l0, inv1 = 1.0f / l1;
    #pragma unroll
    for (int nt = 0; nt < 8; nt++) {
        int c = nt*8 + 2*lr;
        size_t base0 = ((size_t)(b*SS + grow0))*DD + h*DKK + c;
        size_t base1 = ((size_t)(b*SS + grow1))*DD + h*DKK + c;
        float2 v0; v0.x = o[nt][0]*inv0; v0.y = o[nt][1]*inv0;
        float2 v1; v1.x = o[nt][2]*inv1; v1.y = o[nt][3]*inv1;
        *(float2*)(g_AO + base0) = v0;
        *(float2*)(g_AO + base1) = v1;
    }
}

// ---------------------------------------------------------------------------
// Output projection (NT): out[m,n] = AO[m,:] . Wo[n,:] + bo[n]
// ---------------------------------------------------------------------------
__global__ __launch_bounds__(256)
void outproj_mma_kernel(const float* __restrict__ Wo,
                        const float* __restrict__ bo,
                        float* __restrict__ out)
{
    __shared__ float As[128*36];
    __shared__ float Ws[64*36];

    const int n0   = blockIdx.x * 64;
    const int row0 = blockIdx.y * 128;
    const int tid  = threadIdx.x;
    const int warp = tid >> 5;
    const int lane = tid & 31;
    const int wm   = warp >> 1;
    const int wn   = warp & 1;
    const int lq   = lane >> 2;
    const int lr   = lane & 3;

    float acc[2][4][4];
    #pragma unroll
    for (int mt = 0; mt < 2; mt++)
        #pragma unroll
        for (int nt = 0; nt < 4; nt++)
            #pragma unroll
            for (int i = 0; i < 4; i++) acc[mt][nt][i] = 0.0f;

    for (int kt = 0; kt < DD; kt += 32) {
        #pragma unroll
        for (int i = 0; i < 4; i++) {
            int idx = tid + i*256;
            int r = idx >> 3, c4 = idx & 7;
            float4 v = *(const float4*)(g_AO + (size_t)(row0 + r)*DD + kt + c4*4);
            v.x = tf32r(v.x); v.y = tf32r(v.y); v.z = tf32r(v.z); v.w = tf32r(v.w);
            *(float4*)&As[r*36 + c4*4] = v;
        }
        #pragma unroll
        for (int i = 0; i < 2; i++) {
            int idx = tid + i*256;
            int r = idx >> 3, c4 = idx & 7;
            float4 v = *(const float4*)(Wo + (size_t)(n0 + r)*DD + kt + c4*4);
            v.x = tf32r(v.x); v.y = tf32r(v.y); v.z = tf32r(v.z); v.w = tf32r(v.w);
            *(float4*)&Ws[r*36 + c4*4] = v;
        }
        __syncthreads();

        #pragma unroll
        for (int ks = 0; ks < 4; ks++) {
            int kb = ks*8;
            float a[2][4];
            #pragma unroll
            for (int mt = 0; mt < 2; mt++) {
                int ar = wm*32 + mt*16 + lq;
                a[mt][0] = As[ar*36 + kb + lr];
                a[mt][1] = As[(ar+8)*36 + kb + lr];
                a[mt][2] = As[ar*36 + kb + 4 + lr];
                a[mt][3] = As[(ar+8)*36 + kb + 4 + lr];
            }
            #pragma unroll
            for (int nt = 0; nt < 4; nt++) {
                int nc = wn*32 + nt*8 + lq;
                float b0 = Ws[nc*36 + kb + lr];
                float b1 = Ws[nc*36 + kb + 4 + lr];
                #pragma unroll
                for (int mt = 0; mt < 2; mt++)
                    mma8(acc[mt][nt], a[mt][0], a[mt][1], a[mt][2], a[mt][3], b0, b1);
            }
        }
        __syncthreads();
    }

    #pragma unroll
    for (int nt = 0; nt < 4; nt++) {
        int col = n0 + wn*32 + nt*8 + 2*lr;
        float bv0 = bo[col], bv1 = bo[col+1];
        #pragma unroll
        for (int mt = 0; mt < 2; mt++) {
            #pragma unroll
            for (int half = 0; half < 2; half++) {
                size_t grow = row0 + wm*32 + mt*16 + lq + half*8;
                float2 v;
                v.x = acc[mt][nt][half*2+0] + bv0;
                v.y = acc[mt][nt][half*2+1] + bv1;
                *(float2*)(out + grow*DD + col) = v;
            }
        }
    }
}

// ---------------------------------------------------------------------------
extern "C" void kernel_launch(void* const* d_in, const int* in_sizes, int n_in,
                              void* d_out, int out_size)
{
    const float* ctx  = (const float*)d_in[0];
    const float* val  = (const float*)d_in[1];
    const int*   mask = (const int*)  d_in[2];
    const float* Wq   = (const float*)d_in[3];
    const float* bq   = (const float*)d_in[4];
    const float* Wk   = (const float*)d_in[5];
    const float* bk   = (const float*)d_in[6];
    const float* Wv   = (const float*)d_in[7];
    const float* bv   = (const float*)d_in[8];
    const float* Wo   = (const float*)d_in[9];
    const float* bo   = (const float*)d_in[10];
    float* out = (float*)d_out;
    (void)in_sizes; (void)n_in; (void)out_size;

    mask_bits_kernel<<<SS, 256>>>(mask);

    // projections: 2 heads per CTA
    dim3 pgrid(MM / 128, HH / 2);
    proj2_mma_kernel<0><<<pgrid, 256>>>(ctx, Wq, bq);
    proj2_mma_kernel<1><<<pgrid, 256>>>(ctx, Wk, bk);
    proj2_mma_kernel<2><<<pgrid, 256>>>(val, Wv, bv);

    // attention
    int attn_smem = (4*64 + 128) * PADK * (int)sizeof(float);   // 104448
    cudaFuncSetAttribute(attn_mma_kernel, cudaFuncAttributeMaxDynamicSharedMemorySize, attn_smem);
    dim3 agrid(SS / 128, BB * HH);
    attn_mma_kernel<<<agrid, 256, attn_smem>>>();

    // output projection
    dim3 ogrid(DD / 64, MM / 128);
    outproj_mma_kernel<<<ogrid, 256>>>(Wo, bo, out);
}

// round 6
// speedup vs baseline: 2.5718x; 2.0653x over previous
#include <cuda_runtime.h>
#include <cuda_fp16.h>
#include <cstdint>
#include <math.h>

#define BB  4
#define SS  2048
#define DD  1024
#define HH  16
#define DKK 64
#define MM  (BB*SS)

// Static device scratch (half precision intermediates)
__device__ __half   g_Qh[(size_t)BB*HH*SS*DKK];
__device__ __half   g_Kh[(size_t)BB*HH*SS*DKK];
__device__ __half   g_Vh[(size_t)BB*HH*SS*DKK];
__device__ __half   g_AOh[(size_t)BB*SS*DD];
__device__ unsigned g_maskbits[SS * (SS/32)];

// ---------------------------------------------------------------------------
__device__ __forceinline__ float fexp2(float x) {
    float y;
    asm("ex2.approx.ftz.f32 %0, %1;" : "=f"(y) : "f"(x));
    return y;
}
__device__ __forceinline__ unsigned smem_u32(const void* p) {
    return (unsigned)__cvta_generic_to_shared(p);
}
__device__ __forceinline__ void ldsm4(unsigned& r0, unsigned& r1, unsigned& r2, unsigned& r3,
                                      unsigned addr) {
    asm volatile("ldmatrix.sync.aligned.m8n8.x4.shared.b16 {%0,%1,%2,%3}, [%4];"
                 : "=r"(r0), "=r"(r1), "=r"(r2), "=r"(r3) : "r"(addr));
}
__device__ __forceinline__ void ldsm4t(unsigned& r0, unsigned& r1, unsigned& r2, unsigned& r3,
                                       unsigned addr) {
    asm volatile("ldmatrix.sync.aligned.m8n8.x4.trans.shared.b16 {%0,%1,%2,%3}, [%4];"
                 : "=r"(r0), "=r"(r1), "=r"(r2), "=r"(r3) : "r"(addr));
}
__device__ __forceinline__ void mma16(float* c, unsigned a0, unsigned a1, unsigned a2, unsigned a3,
                                      unsigned b0, unsigned b1) {
    asm volatile(
        "mma.sync.aligned.m16n8k16.row.col.f32.f16.f16.f32 "
        "{%0,%1,%2,%3},{%4,%5,%6,%7},{%8,%9},{%0,%1,%2,%3};"
        : "+f"(c[0]), "+f"(c[1]), "+f"(c[2]), "+f"(c[3])
        : "r"(a0), "r"(a1), "r"(a2), "r"(a3), "r"(b0), "r"(b1));
}
__device__ __forceinline__ void cp16(unsigned dst, const void* src) {
    asm volatile("cp.async.cg.shared.global [%0], [%1], 16;" :: "r"(dst), "l"(src));
}
__device__ __forceinline__ void cp_commit() { asm volatile("cp.async.commit_group;"); }
__device__ __forceinline__ void cp_wait0()  { asm volatile("cp.async.wait_group 0;"); }
__device__ __forceinline__ void cp_wait1()  { asm volatile("cp.async.wait_group 1;"); }

// tile rows = 64 halfs (128B = 8 chunks of 16B). XOR swizzle: chunk c of row r at c^(r&7).
__device__ __forceinline__ unsigned tile_addr(unsigned base, int r, int c) {
    return base + (unsigned)(r*128 + (((c) ^ (r & 7)) << 4));
}
__device__ __forceinline__ unsigned h2u(__half2 h) {
    return *reinterpret_cast<unsigned*>(&h);
}
// load 8 f32 from gmem, convert to 8 halfs, store one swizzled 16B chunk
__device__ __forceinline__ void cvt_chunk(__half* tile, int r, int c, const float* src) {
    float4 v0 = *(const float4*)(src);
    float4 v1 = *(const float4*)(src + 4);
    uint4 u;
    u.x = h2u(__floats2half2_rn(v0.x, v0.y));
    u.y = h2u(__floats2half2_rn(v0.z, v0.w));
    u.z = h2u(__floats2half2_rn(v1.x, v1.y));
    u.w = h2u(__floats2half2_rn(v1.z, v1.w));
    *(uint4*)((char*)tile + r*128 + (((c) ^ (r & 7)) << 4)) = u;
}

// ---------------------------------------------------------------------------
__global__ void mask_bits_kernel(const int* __restrict__ mask) {
    int row  = blockIdx.x;
    int warp = threadIdx.x >> 5;
    int lane = threadIdx.x & 31;
    for (int w = warp; w < SS/32; w += 8) {
        int m = mask[(size_t)row * SS + w*32 + lane];
        unsigned bits = __ballot_sync(0xffffffffu, m == 1);
        if (lane == 0) g_maskbits[row * (SS/32) + w] = bits;
    }
}

// ---------------------------------------------------------------------------
// Projection: OUT[b,h,s,n] = X[b,s,:] . W[h,:,n] + bias. BM=128, BN=64, BK=64.
// fp16 mma + ldmatrix. One head per CTA. Output stored half.
// ---------------------------------------------------------------------------
template<int WHICH>
__global__ __launch_bounds__(256)
void projh_kernel(const float* __restrict__ X,
                  const float* __restrict__ W,
                  const float* __restrict__ bias)
{
    __shared__ __half Xs[128*64];   // [m][k]
    __shared__ __half Ws[64*64];    // [k][n]

    __half* out = (WHICH == 0) ? g_Qh : (WHICH == 1) ? g_Kh : g_Vh;

    const int h    = blockIdx.y;
    const int row0 = blockIdx.x * 128;
    const int tid  = threadIdx.x;
    const int warp = tid >> 5;
    const int lane = tid & 31;
    const int wm   = warp >> 1;     // 0..3 -> 32 rows
    const int wn   = warp & 1;      // 0..1 -> 32 cols
    const int g    = lane >> 2;
    const int t    = lane & 3;

    const float* Wh = W + (size_t)h * DD * DKK;
    const unsigned xs = smem_u32(Xs);
    const unsigned ws = smem_u32(Ws);

    float acc[2][4][4];
    #pragma unroll
    for (int mt = 0; mt < 2; mt++)
        #pragma unroll
        for (int nt = 0; nt < 4; nt++)
            #pragma unroll
            for (int i = 0; i < 4; i++) acc[mt][nt][i] = 0.0f;

    for (int kt = 0; kt < DD; kt += 64) {
        // X tile 128x64 f32->half (1024 chunks)
        #pragma unroll
        for (int i = 0; i < 4; i++) {
            int idx = tid + i*256;
            int r = idx >> 3, c = idx & 7;
            cvt_chunk(Xs, r, c, X + (size_t)(row0 + r)*DD + kt + c*8);
        }
        // W tile 64x64 f32->half (512 chunks)
        #pragma unroll
        for (int i = 0; i < 2; i++) {
            int idx = tid + i*256;
            int r = idx >> 3, c = idx & 7;
            cvt_chunk(Ws, r, c, Wh + (size_t)(kt + r)*DKK + c*8);
        }
        __syncthreads();

        #pragma unroll
        for (int j = 0; j < 4; j++) {          // ktile of 16
            unsigned af[2][4];
            #pragma unroll
            for (int mt = 0; mt < 2; mt++)
                ldsm4(af[mt][0], af[mt][1], af[mt][2], af[mt][3],
                      tile_addr(xs, wm*32 + mt*16 + (lane & 15), 2*j + (lane >> 4)));
            #pragma unroll
            for (int pp = 0; pp < 2; pp++) {   // n-pair (16 cols)
                int p = wn*2 + pp;
                unsigned b0, b1, b2, b3;
                ldsm4t(b0, b1, b2, b3,
                       tile_addr(ws, 16*j + (lane & 7) + (lane & 8), 2*p + (lane >> 4)));
                #pragma unroll
                for (int mt = 0; mt < 2; mt++) {
                    mma16(acc[mt][pp*2],   af[mt][0], af[mt][1], af[mt][2], af[mt][3], b0, b1);
                    mma16(acc[mt][pp*2+1], af[mt][0], af[mt][1], af[mt][2], af[mt][3], b2, b3);
                }
            }
        }
        __syncthreads();
    }

    // epilogue: +bias, store half [B,H,S,DK]
    #pragma unroll
    for (int nt = 0; nt < 4; nt++) {
        int col = wn*32 + nt*8 + 2*t;
        float bv0 = bias[h*DKK + col], bv1 = bias[h*DKK + col + 1];
        #pragma unroll
        for (int mt = 0; mt < 2; mt++) {
            #pragma unroll
            for (int half_ = 0; half_ < 2; half_++) {
                int grow = row0 + wm*32 + mt*16 + g + half_*8;
                int b = grow / SS, s = grow % SS;
                size_t o = ((size_t)(b*HH + h)*SS + s)*DKK + col;
                __half2 hv = __floats2half2_rn(acc[mt][nt][half_*2] + bv0,
                                               acc[mt][nt][half_*2+1] + bv1);
                *(__half2*)(out + o) = hv;
            }
        }
    }
}

// ---------------------------------------------------------------------------
// Flash attention, BR=128, BC=64, fp16 mma + ldmatrix, P kept in registers.
// ---------------------------------------------------------------------------
__global__ __launch_bounds__(256)
void attn_h_kernel()
{
    __shared__ __half Qs[128*64];          // 16 KB
    __shared__ __half KVs[2][2][64*64];    // 32 KB (buf, K/V)

    const int bh  = blockIdx.y;
    const int qr0 = blockIdx.x * 128;
    const int tid = threadIdx.x;
    const int wm  = tid >> 5;
    const int lane= tid & 31;
    const int g   = lane >> 2;
    const int t   = lane & 3;

    const __half* Qg = g_Qh + (size_t)bh * SS * DKK;
    const __half* Kg = g_Kh + (size_t)bh * SS * DKK;
    const __half* Vg = g_Vh + (size_t)bh * SS * DKK;

    const unsigned qs   = smem_u32(Qs);
    const unsigned kvs  = smem_u32(KVs);
    const int cr = tid >> 2, cc = tid & 3;

    // prologue: Q stage + KV tile 0
    #pragma unroll
    for (int i = 0; i < 4; i++) {
        int idx = tid + i*256;
        int r = idx >> 3, c = idx & 7;
        cp16(tile_addr(qs, r, c), Qg + (size_t)(qr0 + r)*DKK + c*8);
    }
    {
        unsigned kb = kvs, vb = kvs + 8192;
        cp16(tile_addr(kb, cr, cc),   Kg + (size_t)cr*DKK + cc*8);
        cp16(tile_addr(kb, cr, cc+4), Kg + (size_t)cr*DKK + (cc+4)*8);
        cp16(tile_addr(vb, cr, cc),   Vg + (size_t)cr*DKK + cc*8);
        cp16(tile_addr(vb, cr, cc+4), Vg + (size_t)cr*DKK + (cc+4)*8);
    }
    cp_commit();
    cp_wait0();
    __syncthreads();

    // Q fragments (4 ktiles x 4 regs)
    unsigned qf[4][4];
    {
        int m0 = wm*16;
        #pragma unroll
        for (int j = 0; j < 4; j++)
            ldsm4(qf[j][0], qf[j][1], qf[j][2], qf[j][3],
                  tile_addr(qs, m0 + (lane & 15), 2*j + (lane >> 4)));
    }

    float o[8][4];
    float m0_ = -1e30f, m1_ = -1e30f, l0 = 0.0f, l1 = 0.0f;
    #pragma unroll
    for (int nt = 0; nt < 8; nt++)
        #pragma unroll
        for (int i = 0; i < 4; i++) o[nt][i] = 0.0f;

    const int grow0 = qr0 + wm*16 + g;
    const int grow1 = grow0 + 8;
    const float SCL = 0.18033688011112042f;   // 0.125 * log2(e)

    for (int it = 0; it < SS/64; it++) {
        int buf = it & 1;
        unsigned kb = kvs + buf*16384;
        unsigned vb = kb + 8192;

        if (it + 1 < SS/64) {
            const __half* Kn = Kg + (size_t)(it+1)*64*DKK;
            const __half* Vn = Vg + (size_t)(it+1)*64*DKK;
            unsigned kb2 = kvs + (buf^1)*16384, vb2 = kb2 + 8192;
            cp16(tile_addr(kb2, cr, cc),   Kn + (size_t)cr*DKK + cc*8);
            cp16(tile_addr(kb2, cr, cc+4), Kn + (size_t)cr*DKK + (cc+4)*8);
            cp16(tile_addr(vb2, cr, cc),   Vn + (size_t)cr*DKK + cc*8);
            cp16(tile_addr(vb2, cr, cc+4), Vn + (size_t)cr*DKK + (cc+4)*8);
        }
        cp_commit();
        cp_wait1();
        __syncthreads();

        // S = Q . K^T
        float s[8][4];
        #pragma unroll
        for (int nt = 0; nt < 8; nt++)
            #pragma unroll
            for (int i = 0; i < 4; i++) s[nt][i] = 0.0f;

        #pragma unroll
        for (int j = 0; j < 4; j++) {
            #pragma unroll
            for (int p = 0; p < 4; p++) {
                unsigned b0, b1, b2, b3;
                ldsm4(b0, b1, b2, b3,
                      tile_addr(kb, p*16 + (lane & 7) + ((lane & 16) >> 1),
                                2*j + ((lane >> 3) & 1)));
                mma16(s[2*p],   qf[j][0], qf[j][1], qf[j][2], qf[j][3], b0, b1);
                mma16(s[2*p+1], qf[j][0], qf[j][1], qf[j][2], qf[j][3], b2, b3);
            }
        }

        // mask + scale
        int kw = it*2;
        unsigned w0a = g_maskbits[grow0*(SS/32) + kw];
        unsigned w0b = g_maskbits[grow0*(SS/32) + kw + 1];
        unsigned w1a = g_maskbits[grow1*(SS/32) + kw];
        unsigned w1b = g_maskbits[grow1*(SS/32) + kw + 1];
        #pragma unroll
        for (int nt = 0; nt < 8; nt++) {
            int c = nt*8 + 2*t;
            unsigned wr0 = (c < 32) ? w0a : w0b;
            unsigned wr1 = (c < 32) ? w1a : w1b;
            int sh = c & 31;
            s[nt][0] = ((wr0 >> sh)     & 1u) ? -1e9f : s[nt][0]*SCL;
            s[nt][1] = ((wr0 >> (sh+1)) & 1u) ? -1e9f : s[nt][1]*SCL;
            s[nt][2] = ((wr1 >> sh)     & 1u) ? -1e9f : s[nt][2]*SCL;
            s[nt][3] = ((wr1 >> (sh+1)) & 1u) ? -1e9f : s[nt][3]*SCL;
        }

        // online softmax (base-2)
        float mx0 = -1e30f, mx1 = -1e30f;
        #pragma unroll
        for (int nt = 0; nt < 8; nt++) {
            mx0 = fmaxf(mx0, fmaxf(s[nt][0], s[nt][1]));
            mx1 = fmaxf(mx1, fmaxf(s[nt][2], s[nt][3]));
        }
        mx0 = fmaxf(mx0, __shfl_xor_sync(0xffffffffu, mx0, 1));
        mx0 = fmaxf(mx0, __shfl_xor_sync(0xffffffffu, mx0, 2));
        mx1 = fmaxf(mx1, __shfl_xor_sync(0xffffffffu, mx1, 1));
        mx1 = fmaxf(mx1, __shfl_xor_sync(0xffffffffu, mx1, 2));
        float mn0 = fmaxf(m0_, mx0);
        float mn1 = fmaxf(m1_, mx1);
        float sum0 = 0.0f, sum1 = 0.0f;
        #pragma unroll
        for (int nt = 0; nt < 8; nt++) {
            s[nt][0] = fexp2(s[nt][0] - mn0); sum0 += s[nt][0];
            s[nt][1] = fexp2(s[nt][1] - mn0); sum0 += s[nt][1];
            s[nt][2] = fexp2(s[nt][2] - mn1); sum1 += s[nt][2];
            s[nt][3] = fexp2(s[nt][3] - mn1); sum1 += s[nt][3];
        }
        sum0 += __shfl_xor_sync(0xffffffffu, sum0, 1);
        sum0 += __shfl_xor_sync(0xffffffffu, sum0, 2);
        sum1 += __shfl_xor_sync(0xffffffffu, sum1, 1);
        sum1 += __shfl_xor_sync(0xffffffffu, sum1, 2);
        float sc0 = fexp2(m0_ - mn0);
        float sc1 = fexp2(m1_ - mn1);
        l0 = l0*sc0 + sum0;  m0_ = mn0;
        l1 = l1*sc1 + sum1;  m1_ = mn1;
        #pragma unroll
        for (int nt = 0; nt < 8; nt++) {
            o[nt][0] *= sc0; o[nt][1] *= sc0;
            o[nt][2] *= sc1; o[nt][3] *= sc1;
        }

        // P fragments in registers (C-frag -> A-frag identity)
        unsigned pf[4][4];
        #pragma unroll
        for (int j = 0; j < 4; j++) {
            pf[j][0] = h2u(__floats2half2_rn(s[2*j][0],   s[2*j][1]));
            pf[j][1] = h2u(__floats2half2_rn(s[2*j][2],   s[2*j][3]));
            pf[j][2] = h2u(__floats2half2_rn(s[2*j+1][0], s[2*j+1][1]));
            pf[j][3] = h2u(__floats2half2_rn(s[2*j+1][2], s[2*j+1][3]));
        }

        // O += P . V
        #pragma unroll
        for (int j = 0; j < 4; j++) {
            #pragma unroll
            for (int p = 0; p < 4; p++) {
                unsigned b0, b1, b2, b3;
                ldsm4t(b0, b1, b2, b3,
                       tile_addr(vb, 16*j + (lane & 7) + (lane & 8), 2*p + (lane >> 4)));
                mma16(o[2*p],   pf[j][0], pf[j][1], pf[j][2], pf[j][3], b0, b1);
                mma16(o[2*p+1], pf[j][0], pf[j][1], pf[j][2], pf[j][3], b2, b3);
            }
        }
        __syncthreads();
    }

    // epilogue -> concat layout, half
    const int b = bh >> 4, h = bh & 15;
    float inv0 = 1.0f / l0, inv1 = 1.0f / l1;
    #pragma unroll
    for (int nt = 0; nt < 8; nt++) {
        int c = nt*8 + 2*t;
        size_t base0 = ((size_t)(b*SS + grow0))*DD + h*DKK + c;
        size_t base1 = ((size_t)(b*SS + grow1))*DD + h*DKK + c;
        *(__half2*)(g_AOh + base0) = __floats2half2_rn(o[nt][0]*inv0, o[nt][1]*inv0);
        *(__half2*)(g_AOh + base1) = __floats2half2_rn(o[nt][2]*inv1, o[nt][3]*inv1);
    }
}

// ---------------------------------------------------------------------------
// Output projection: out[m,n] = AOh[m,:] . Wo[n,:] + bo[n]. BM=128, BN=64, BK=64.
// ---------------------------------------------------------------------------
__global__ __launch_bounds__(256)
void outprojh_kernel(const float* __restrict__ Wo,
                     const float* __restrict__ bo,
                     float* __restrict__ out)
{
    __shared__ __half As[128*64];   // [m][k] via cp.async
    __shared__ __half Ws[64*64];    // [n][k] converted

    const int n0   = blockIdx.x * 64;
    const int row0 = blockIdx.y * 128;
    const int tid  = threadIdx.x;
    const int warp = tid >> 5;
    const int lane = tid & 31;
    const int wm   = warp >> 1;
    const int wn   = warp & 1;
    const int g    = lane >> 2;
    const int t    = lane & 3;

    const unsigned as_ = smem_u32(As);
    const unsigned ws_ = smem_u32(Ws);

    float acc[2][4][4];
    #pragma unroll
    for (int mt = 0; mt < 2; mt++)
        #pragma unroll
        for (int nt = 0; nt < 4; nt++)
            #pragma unroll
            for (int i = 0; i < 4; i++) acc[mt][nt][i] = 0.0f;

    for (int kt = 0; kt < DD; kt += 64) {
        // As via cp.async (half source)
        #pragma unroll
        for (int i = 0; i < 4; i++) {
            int idx = tid + i*256;
            int r = idx >> 3, c = idx & 7;
            cp16(tile_addr(as_, r, c), g_AOh + (size_t)(row0 + r)*DD + kt + c*8);
        }
        cp_commit();
        // Ws f32->half
        #pragma unroll
        for (int i = 0; i < 2; i++) {
            int idx = tid + i*256;
            int r = idx >> 3, c = idx & 7;
            cvt_chunk(Ws, r, c, Wo + (size_t)(n0 + r)*DD + kt + c*8);
        }
        cp_wait0();
        __syncthreads();

        #pragma unroll
        for (int j = 0; j < 4; j++) {
            unsigned af[2][4];
            #pragma unroll
            for (int mt = 0; mt < 2; mt++)
                ldsm4(af[mt][0], af[mt][1], af[mt][2], af[mt][3],
                      tile_addr(as_, wm*32 + mt*16 + (lane & 15), 2*j + (lane >> 4)));
            #pragma unroll
            for (int pp = 0; pp < 2; pp++) {
                int p = wn*2 + pp;
                unsigned b0, b1, b2, b3;
                ldsm4(b0, b1, b2, b3,
                      tile_addr(ws_, p*16 + (lane & 7) + ((lane & 16) >> 1),
                                2*j + ((lane >> 3) & 1)));
                #pragma unroll
                for (int mt = 0; mt < 2; mt++) {
                    mma16(acc[mt][pp*2],   af[mt][0], af[mt][1], af[mt][2], af[mt][3], b0, b1);
                    mma16(acc[mt][pp*2+1], af[mt][0], af[mt][1], af[mt][2], af[mt][3], b2, b3);
                }
            }
        }
        __syncthreads();
    }

    #pragma unroll
    for (int nt = 0; nt < 4; nt++) {
        int col = n0 + wn*32 + nt*8 + 2*t;
        float bv0 = bo[col], bv1 = bo[col+1];
        #pragma unroll
        for (int mt = 0; mt < 2; mt++) {
            #pragma unroll
            for (int half_ = 0; half_ < 2; half_++) {
                size_t grow = row0 + wm*32 + mt*16 + g + half_*8;
                float2 v;
                v.x = acc[mt][nt][half_*2+0] + bv0;
                v.y = acc[mt][nt][half_*2+1] + bv1;
                *(float2*)(out + grow*DD + col) = v;
            }
        }
    }
}

// ---------------------------------------------------------------------------
extern "C" void kernel_launch(void* const* d_in, const int* in_sizes, int n_in,
                              void* d_out, int out_size)
{
    const float* ctx  = (const float*)d_in[0];
    const float* val  = (const float*)d_in[1];
    const int*   mask = (const int*)  d_in[2];
    const float* Wq   = (const float*)d_in[3];
    const float* bq   = (const float*)d_in[4];
    const float* Wk   = (const float*)d_in[5];
    const float* bk   = (const float*)d_in[6];
    const float* Wv   = (const float*)d_in[7];
    const float* bv   = (const float*)d_in[8];
    const float* Wo   = (const float*)d_in[9];
    const float* bo   = (const float*)d_in[10];
    float* out = (float*)d_out;
    (void)in_sizes; (void)n_in; (void)out_size;

    mask_bits_kernel<<<SS, 256>>>(mask);

    dim3 pgrid(MM / 128, HH);
    projh_kernel<0><<<pgrid, 256>>>(ctx, Wq, bq);
    projh_kernel<1><<<pgrid, 256>>>(ctx, Wk, bk);
    projh_kernel<2><<<pgrid, 256>>>(val, Wv, bv);

    dim3 agrid(SS / 128, BB * HH);
    attn_h_kernel<<<agrid, 256>>>();

    dim3 ogrid(DD / 64, MM / 128);
    outprojh_kernel<<<ogrid, 256>>>(Wo, bo, out);
}

// round 7
// speedup vs baseline: 3.4778x; 1.3523x over previous
#include <cuda_runtime.h>
#include <cuda_fp16.h>
#include <cstdint>
#include <math.h>

#define BB  4
#define SS  2048
#define DD  1024
#define HH  16
#define DKK 64
#define MM  (BB*SS)

// Static device scratch (half precision)
__device__ __half   g_Xch[(size_t)MM*DD];        // ctx as half
__device__ __half   g_Xvh[(size_t)MM*DD];        // val as half
__device__ __half   g_Wqh[(size_t)HH*DD*DKK];
__device__ __half   g_Wkh[(size_t)HH*DD*DKK];
__device__ __half   g_Wvh[(size_t)HH*DD*DKK];
__device__ __half   g_Woh[(size_t)DD*DD];
__device__ __half   g_Qh[(size_t)BB*HH*SS*DKK];
__device__ __half   g_Kh[(size_t)BB*HH*SS*DKK];
__device__ __half   g_Vh[(size_t)BB*HH*SS*DKK];
__device__ __half   g_AOh[(size_t)BB*SS*DD];
__device__ unsigned g_maskbits[SS * (SS/32)];

// ---------------------------------------------------------------------------
__device__ __forceinline__ float fexp2(float x) {
    float y;
    asm("ex2.approx.ftz.f32 %0, %1;" : "=f"(y) : "f"(x));
    return y;
}
__device__ __forceinline__ unsigned smem_u32(const void* p) {
    return (unsigned)__cvta_generic_to_shared(p);
}
__device__ __forceinline__ void ldsm4(unsigned& r0, unsigned& r1, unsigned& r2, unsigned& r3,
                                      unsigned addr) {
    asm volatile("ldmatrix.sync.aligned.m8n8.x4.shared.b16 {%0,%1,%2,%3}, [%4];"
                 : "=r"(r0), "=r"(r1), "=r"(r2), "=r"(r3) : "r"(addr));
}
__device__ __forceinline__ void ldsm4t(unsigned& r0, unsigned& r1, unsigned& r2, unsigned& r3,
                                       unsigned addr) {
    asm volatile("ldmatrix.sync.aligned.m8n8.x4.trans.shared.b16 {%0,%1,%2,%3}, [%4];"
                 : "=r"(r0), "=r"(r1), "=r"(r2), "=r"(r3) : "r"(addr));
}
__device__ __forceinline__ void mma16(float* c, unsigned a0, unsigned a1, unsigned a2, unsigned a3,
                                      unsigned b0, unsigned b1) {
    asm volatile(
        "mma.sync.aligned.m16n8k16.row.col.f32.f16.f16.f32 "
        "{%0,%1,%2,%3},{%4,%5,%6,%7},{%8,%9},{%0,%1,%2,%3};"
        : "+f"(c[0]), "+f"(c[1]), "+f"(c[2]), "+f"(c[3])
        : "r"(a0), "r"(a1), "r"(a2), "r"(a3), "r"(b0), "r"(b1));
}
__device__ __forceinline__ void cp16(unsigned dst, const void* src) {
    asm volatile("cp.async.cg.shared.global [%0], [%1], 16;" :: "r"(dst), "l"(src));
}
__device__ __forceinline__ void cp_commit() { asm volatile("cp.async.commit_group;"); }
__device__ __forceinline__ void cp_wait0()  { asm volatile("cp.async.wait_group 0;"); }
__device__ __forceinline__ void cp_wait1()  { asm volatile("cp.async.wait_group 1;"); }

// tile rows = 64 halfs (128B = 8 chunks of 16B). XOR swizzle: chunk c of row r at c^(r&7)
__device__ __forceinline__ unsigned tile_addr(unsigned base, int r, int c) {
    return base + (unsigned)(r*128 + (((c) ^ (r & 7)) << 4));
}
__device__ __forceinline__ unsigned h2u(__half2 h) {
    return *reinterpret_cast<unsigned*>(&h);
}

// ---------------------------------------------------------------------------
// f32 -> f16 bulk conversion (8 elements / thread)
// ---------------------------------------------------------------------------
__global__ void f2h_kernel(const float* __restrict__ src, __half* __restrict__ dst, int n8) {
    int i = blockIdx.x * blockDim.x + threadIdx.x;
    if (i < n8) {
        float4 v0 = *(const float4*)(src + (size_t)i*8);
        float4 v1 = *(const float4*)(src + (size_t)i*8 + 4);
        uint4 u;
        u.x = h2u(__floats2half2_rn(v0.x, v0.y));
        u.y = h2u(__floats2half2_rn(v0.z, v0.w));
        u.z = h2u(__floats2half2_rn(v1.x, v1.y));
        u.w = h2u(__floats2half2_rn(v1.z, v1.w));
        *(uint4*)(dst + (size_t)i*8) = u;
    }
}

// ---------------------------------------------------------------------------
__global__ void mask_bits_kernel(const int* __restrict__ mask) {
    int row  = blockIdx.x;
    int warp = threadIdx.x >> 5;
    int lane = threadIdx.x & 31;
    for (int w = warp; w < SS/32; w += 8) {
        int m = mask[(size_t)row * SS + w*32 + lane];
        unsigned bits = __ballot_sync(0xffffffffu, m == 1);
        if (lane == 0) g_maskbits[row * (SS/32) + w] = bits;
    }
}

// ---------------------------------------------------------------------------
// Projection (all-half, cp.async, K-stage double buffer).
// OUT[b,h,s,n] = Xh[b,s,:] . Wh[h,:,n] + bias. BM=128, BN=64, BK=64.
// ---------------------------------------------------------------------------
template<int WHICH>
__global__ __launch_bounds__(256)
void projh_kernel(const float* __restrict__ bias)
{
    extern __shared__ __half sh[];
    __half* Xs = sh;                 // 2 x 128x64
    __half* Ws = sh + 2*128*64;      // 2 x 64x64

    const __half* Xh = (WHICH == 2) ? g_Xvh : g_Xch;
    const __half* Wg = (WHICH == 0) ? g_Wqh : (WHICH == 1) ? g_Wkh : g_Wvh;
    __half* out = (WHICH == 0) ? g_Qh : (WHICH == 1) ? g_Kh : g_Vh;

    const int h    = blockIdx.y;
    const int row0 = blockIdx.x * 128;
    const int tid  = threadIdx.x;
    const int warp = tid >> 5;
    const int lane = tid & 31;
    const int wm   = warp >> 1;
    const int wn   = warp & 1;
    const int g    = lane >> 2;
    const int t    = lane & 3;

    const __half* Wh = Wg + (size_t)h * DD * DKK;
    const unsigned xs = smem_u32(Xs);
    const unsigned ws = smem_u32(Ws);

    float acc[2][4][4];
    #pragma unroll
    for (int mt = 0; mt < 2; mt++)
        #pragma unroll
        for (int nt = 0; nt < 4; nt++)
            #pragma unroll
            for (int i = 0; i < 4; i++) acc[mt][nt][i] = 0.0f;

    // stage loader: X 1024 chunks, W 512 chunks
    auto load_stage = [&](int kt, int buf) {
        unsigned xb = xs + buf*128*64*2;
        unsigned wb = ws + buf*64*64*2;
        #pragma unroll
        for (int i = 0; i < 4; i++) {
            int idx = tid + i*256;
            int r = idx >> 3, c = idx & 7;
            cp16(tile_addr(xb, r, c), Xh + (size_t)(row0 + r)*DD + kt + c*8);
        }
        #pragma unroll
        for (int i = 0; i < 2; i++) {
            int idx = tid + i*256;
            int r = idx >> 3, c = idx & 7;
            cp16(tile_addr(wb, r, c), Wh + (size_t)(kt + r)*DKK + c*8);
        }
    };

    load_stage(0, 0);
    cp_commit();

    const int NS = DD / 64;   // 16 stages
    for (int s = 0; s < NS; s++) {
        int buf = s & 1;
        if (s + 1 < NS) load_stage((s+1)*64, buf^1);
        cp_commit();
        cp_wait1();
        __syncthreads();

        unsigned xb = xs + buf*128*64*2;
        unsigned wb = ws + buf*64*64*2;

        #pragma unroll
        for (int j = 0; j < 4; j++) {
            unsigned af[2][4];
            #pragma unroll
            for (int mt = 0; mt < 2; mt++)
                ldsm4(af[mt][0], af[mt][1], af[mt][2], af[mt][3],
                      tile_addr(xb, wm*32 + mt*16 + (lane & 15), 2*j + (lane >> 4)));
            #pragma unroll
            for (int pp = 0; pp < 2; pp++) {
                int p = wn*2 + pp;
                unsigned b0, b1, b2, b3;
                ldsm4t(b0, b1, b2, b3,
                       tile_addr(wb, 16*j + (lane & 7) + (lane & 8), 2*p + (lane >> 4)));
                #pragma unroll
                for (int mt = 0; mt < 2; mt++) {
                    mma16(acc[mt][pp*2],   af[mt][0], af[mt][1], af[mt][2], af[mt][3], b0, b1);
                    mma16(acc[mt][pp*2+1], af[mt][0], af[mt][1], af[mt][2], af[mt][3], b2, b3);
                }
            }
        }
        __syncthreads();
    }

    #pragma unroll
    for (int nt = 0; nt < 4; nt++) {
        int col = wn*32 + nt*8 + 2*t;
        float bv0 = bias[h*DKK + col], bv1 = bias[h*DKK + col + 1];
        #pragma unroll
        for (int mt = 0; mt < 2; mt++) {
            #pragma unroll
            for (int half_ = 0; half_ < 2; half_++) {
                int grow = row0 + wm*32 + mt*16 + g + half_*8;
                int b = grow / SS, ss = grow % SS;
                size_t o = ((size_t)(b*HH + h)*SS + ss)*DKK + col;
                *(__half2*)(out + o) = __floats2half2_rn(acc[mt][nt][half_*2] + bv0,
                                                         acc[mt][nt][half_*2+1] + bv1);
            }
        }
    }
}

// ---------------------------------------------------------------------------
// Flash attention, BR=128, BC=64 (unchanged from R6).
// ---------------------------------------------------------------------------
__global__ __launch_bounds__(256)
void attn_h_kernel()
{
    __shared__ __half Qs[128*64];
    __shared__ __half KVs[2][2][64*64];

    const int bh  = blockIdx.y;
    const int qr0 = blockIdx.x * 128;
    const int tid = threadIdx.x;
    const int wm  = tid >> 5;
    const int lane= tid & 31;
    const int g   = lane >> 2;
    const int t   = lane & 3;

    const __half* Qg = g_Qh + (size_t)bh * SS * DKK;
    const __half* Kg = g_Kh + (size_t)bh * SS * DKK;
    const __half* Vg = g_Vh + (size_t)bh * SS * DKK;

    const unsigned qs   = smem_u32(Qs);
    const unsigned kvs  = smem_u32(KVs);
    const int cr = tid >> 2, cc = tid & 3;

    #pragma unroll
    for (int i = 0; i < 4; i++) {
        int idx = tid + i*256;
        int r = idx >> 3, c = idx & 7;
        cp16(tile_addr(qs, r, c), Qg + (size_t)(qr0 + r)*DKK + c*8);
    }
    {
        unsigned kb = kvs, vb = kvs + 8192;
        cp16(tile_addr(kb, cr, cc),   Kg + (size_t)cr*DKK + cc*8);
        cp16(tile_addr(kb, cr, cc+4), Kg + (size_t)cr*DKK + (cc+4)*8);
        cp16(tile_addr(vb, cr, cc),   Vg + (size_t)cr*DKK + cc*8);
        cp16(tile_addr(vb, cr, cc+4), Vg + (size_t)cr*DKK + (cc+4)*8);
    }
    cp_commit();
    cp_wait0();
    __syncthreads();

    unsigned qf[4][4];
    {
        int m0 = wm*16;
        #pragma unroll
        for (int j = 0; j < 4; j++)
            ldsm4(qf[j][0], qf[j][1], qf[j][2], qf[j][3],
                  tile_addr(qs, m0 + (lane & 15), 2*j + (lane >> 4)));
    }

    float o[8][4];
    float m0_ = -1e30f, m1_ = -1e30f, l0 = 0.0f, l1 = 0.0f;
    #pragma unroll
    for (int nt = 0; nt < 8; nt++)
        #pragma unroll
        for (int i = 0; i < 4; i++) o[nt][i] = 0.0f;

    const int grow0 = qr0 + wm*16 + g;
    const int grow1 = grow0 + 8;
    const float SCL = 0.18033688011112042f;

    for (int it = 0; it < SS/64; it++) {
        int buf = it & 1;
        unsigned kb = kvs + buf*16384;
        unsigned vb = kb + 8192;

        if (it + 1 < SS/64) {
            const __half* Kn = Kg + (size_t)(it+1)*64*DKK;
            const __half* Vn = Vg + (size_t)(it+1)*64*DKK;
            unsigned kb2 = kvs + (buf^1)*16384, vb2 = kb2 + 8192;
            cp16(tile_addr(kb2, cr, cc),   Kn + (size_t)cr*DKK + cc*8);
            cp16(tile_addr(kb2, cr, cc+4), Kn + (size_t)cr*DKK + (cc+4)*8);
            cp16(tile_addr(vb2, cr, cc),   Vn + (size_t)cr*DKK + cc*8);
            cp16(tile_addr(vb2, cr, cc+4), Vn + (size_t)cr*DKK + (cc+4)*8);
        }
        cp_commit();
        cp_wait1();
        __syncthreads();

        float s[8][4];
        #pragma unroll
        for (int nt = 0; nt < 8; nt++)
            #pragma unroll
            for (int i = 0; i < 4; i++) s[nt][i] = 0.0f;

        #pragma unroll
        for (int j = 0; j < 4; j++) {
            #pragma unroll
            for (int p = 0; p < 4; p++) {
                unsigned b0, b1, b2, b3;
                ldsm4(b0, b1, b2, b3,
                      tile_addr(kb, p*16 + (lane & 7) + ((lane & 16) >> 1),
                                2*j + ((lane >> 3) & 1)));
                mma16(s[2*p],   qf[j][0], qf[j][1], qf[j][2], qf[j][3], b0, b1);
                mma16(s[2*p+1], qf[j][0], qf[j][1], qf[j][2], qf[j][3], b2, b3);
            }
        }

        int kw = it*2;
        unsigned w0a = g_maskbits[grow0*(SS/32) + kw];
        unsigned w0b = g_maskbits[grow0*(SS/32) + kw + 1];
        unsigned w1a = g_maskbits[grow1*(SS/32) + kw];
        unsigned w1b = g_maskbits[grow1*(SS/32) + kw + 1];
        #pragma unroll
        for (int nt = 0; nt < 8; nt++) {
            int c = nt*8 + 2*t;
            unsigned wr0 = (c < 32) ? w0a : w0b;
            unsigned wr1 = (c < 32) ? w1a : w1b;
            int sh_ = c & 31;
            s[nt][0] = ((wr0 >> sh_)     & 1u) ? -1e9f : s[nt][0]*SCL;
            s[nt][1] = ((wr0 >> (sh_+1)) & 1u) ? -1e9f : s[nt][1]*SCL;
            s[nt][2] = ((wr1 >> sh_)     & 1u) ? -1e9f : s[nt][2]*SCL;
            s[nt][3] = ((wr1 >> (sh_+1)) & 1u) ? -1e9f : s[nt][3]*SCL;
        }

        float mx0 = -1e30f, mx1 = -1e30f;
        #pragma unroll
        for (int nt = 0; nt < 8; nt++) {
            mx0 = fmaxf(mx0, fmaxf(s[nt][0], s[nt][1]));
            mx1 = fmaxf(mx1, fmaxf(s[nt][2], s[nt][3]));
        }
        mx0 = fmaxf(mx0, __shfl_xor_sync(0xffffffffu, mx0, 1));
        mx0 = fmaxf(mx0, __shfl_xor_sync(0xffffffffu, mx0, 2));
        mx1 = fmaxf(mx1, __shfl_xor_sync(0xffffffffu, mx1, 1));
        mx1 = fmaxf(mx1, __shfl_xor_sync(0xffffffffu, mx1, 2));
        float mn0 = fmaxf(m0_, mx0);
        float mn1 = fmaxf(m1_, mx1);
        float sum0 = 0.0f, sum1 = 0.0f;
        #pragma unroll
        for (int nt = 0; nt < 8; nt++) {
            s[nt][0] = fexp2(s[nt][0] - mn0); sum0 += s[nt][0];
            s[nt][1] = fexp2(s[nt][1] - mn0); sum0 += s[nt][1];
            s[nt][2] = fexp2(s[nt][2] - mn1); sum1 += s[nt][2];
            s[nt][3] = fexp2(s[nt][3] - mn1); sum1 += s[nt][3];
        }
        sum0 += __shfl_xor_sync(0xffffffffu, sum0, 1);
        sum0 += __shfl_xor_sync(0xffffffffu, sum0, 2);
        sum1 += __shfl_xor_sync(0xffffffffu, sum1, 1);
        sum1 += __shfl_xor_sync(0xffffffffu, sum1, 2);
        float sc0 = fexp2(m0_ - mn0);
        float sc1 = fexp2(m1_ - mn1);
        l0 = l0*sc0 + sum0;  m0_ = mn0;
        l1 = l1*sc1 + sum1;  m1_ = mn1;
        #pragma unroll
        for (int nt = 0; nt < 8; nt++) {
            o[nt][0] *= sc0; o[nt][1] *= sc0;
            o[nt][2] *= sc1; o[nt][3] *= sc1;
        }

        unsigned pf[4][4];
        #pragma unroll
        for (int j = 0; j < 4; j++) {
            pf[j][0] = h2u(__floats2half2_rn(s[2*j][0],   s[2*j][1]));
            pf[j][1] = h2u(__floats2half2_rn(s[2*j][2],   s[2*j][3]));
            pf[j][2] = h2u(__floats2half2_rn(s[2*j+1][0], s[2*j+1][1]));
            pf[j][3] = h2u(__floats2half2_rn(s[2*j+1][2], s[2*j+1][3]));
        }

        #pragma unroll
        for (int j = 0; j < 4; j++) {
            #pragma unroll
            for (int p = 0; p < 4; p++) {
                unsigned b0, b1, b2, b3;
                ldsm4t(b0, b1, b2, b3,
                       tile_addr(vb, 16*j + (lane & 7) + (lane & 8), 2*p + (lane >> 4)));
                mma16(o[2*p],   pf[j][0], pf[j][1], pf[j][2], pf[j][3], b0, b1);
                mma16(o[2*p+1], pf[j][0], pf[j][1], pf[j][2], pf[j][3], b2, b3);
            }
        }
        __syncthreads();
    }

    const int b = bh >> 4, h = bh & 15;
    float inv0 = 1.0f / l0, inv1 = 1.0f / l1;
    #pragma unroll
    for (int nt = 0; nt < 8; nt++) {
        int c = nt*8 + 2*t;
        size_t base0 = ((size_t)(b*SS + grow0))*DD + h*DKK + c;
        size_t base1 = ((size_t)(b*SS + grow1))*DD + h*DKK + c;
        *(__half2*)(g_AOh + base0) = __floats2half2_rn(o[nt][0]*inv0, o[nt][1]*inv0);
        *(__half2*)(g_AOh + base1) = __floats2half2_rn(o[nt][2]*inv1, o[nt][3]*inv1);
    }
}

// ---------------------------------------------------------------------------
// Output projection (all-half, cp.async, double buffer). BM=128, BN=64, BK=64.
// ---------------------------------------------------------------------------
__global__ __launch_bounds__(256)
void outprojh_kernel(const float* __restrict__ bo,
                     float* __restrict__ out)
{
    extern __shared__ __half sh[];
    __half* As = sh;                 // 2 x 128x64
    __half* Ws = sh + 2*128*64;      // 2 x 64x64 ([n][k])

    const int n0   = blockIdx.x * 64;
    const int row0 = blockIdx.y * 128;
    const int tid  = threadIdx.x;
    const int warp = tid >> 5;
    const int lane = tid & 31;
    const int wm   = warp >> 1;
    const int wn   = warp & 1;
    const int g    = lane >> 2;
    const int t    = lane & 3;

    const unsigned as_ = smem_u32(As);
    const unsigned ws_ = smem_u32(Ws);

    float acc[2][4][4];
    #pragma unroll
    for (int mt = 0; mt < 2; mt++)
        #pragma unroll
        for (int nt = 0; nt < 4; nt++)
            #pragma unroll
            for (int i = 0; i < 4; i++) acc[mt][nt][i] = 0.0f;

    auto load_stage = [&](int kt, int buf) {
        unsigned ab = as_ + buf*128*64*2;
        unsigned wb = ws_ + buf*64*64*2;
        #pragma unroll
        for (int i = 0; i < 4; i++) {
            int idx = tid + i*256;
            int r = idx >> 3, c = idx & 7;
            cp16(tile_addr(ab, r, c), g_AOh + (size_t)(row0 + r)*DD + kt + c*8);
        }
        #pragma unroll
        for (int i = 0; i < 2; i++) {
            int idx = tid + i*256;
            int r = idx >> 3, c = idx & 7;
            cp16(tile_addr(wb, r, c), g_Woh + (size_t)(n0 + r)*DD + kt + c*8);
        }
    };

    load_stage(0, 0);
    cp_commit();

    const int NS = DD / 64;
    for (int s = 0; s < NS; s++) {
        int buf = s & 1;
        if (s + 1 < NS) load_stage((s+1)*64, buf^1);
        cp_commit();
        cp_wait1();
        __syncthreads();

        unsigned ab = as_ + buf*128*64*2;
        unsigned wb = ws_ + buf*64*64*2;

        #pragma unroll
        for (int j = 0; j < 4; j++) {
            unsigned af[2][4];
            #pragma unroll
            for (int mt = 0; mt < 2; mt++)
                ldsm4(af[mt][0], af[mt][1], af[mt][2], af[mt][3],
                      tile_addr(ab, wm*32 + mt*16 + (lane & 15), 2*j + (lane >> 4)));
            #pragma unroll
            for (int pp = 0; pp < 2; pp++) {
                int p = wn*2 + pp;
                unsigned b0, b1, b2, b3;
                ldsm4(b0, b1, b2, b3,
                      tile_addr(wb, p*16 + (lane & 7) + ((lane & 16) >> 1),
                                2*j + ((lane >> 3) & 1)));
                #pragma unroll
                for (int mt = 0; mt < 2; mt++) {
                    mma16(acc[mt][pp*2],   af[mt][0], af[mt][1], af[mt][2], af[mt][3], b0, b1);
                    mma16(acc[mt][pp*2+1], af[mt][0], af[mt][1], af[mt][2], af[mt][3], b2, b3);
                }
            }
        }
        __syncthreads();
    }

    #pragma unroll
    for (int nt = 0; nt < 4; nt++) {
        int col = n0 + wn*32 + nt*8 + 2*t;
        float bv0 = bo[col], bv1 = bo[col+1];
        #pragma unroll
        for (int mt = 0; mt < 2; mt++) {
            #pragma unroll
            for (int half_ = 0; half_ < 2; half_++) {
                size_t grow = row0 + wm*32 + mt*16 + g + half_*8;
                float2 v;
                v.x = acc[mt][nt][half_*2+0] + bv0;
                v.y = acc[mt][nt][half_*2+1] + bv1;
                *(float2*)(out + grow*DD + col) = v;
            }
        }
    }
}

// ---------------------------------------------------------------------------
extern "C" void kernel_launch(void* const* d_in, const int* in_sizes, int n_in,
                              void* d_out, int out_size)
{
    const float* ctx  = (const float*)d_in[0];
    const float* val  = (const float*)d_in[1];
    const int*   mask = (const int*)  d_in[2];
    const float* Wq   = (const float*)d_in[3];
    const float* bq   = (const float*)d_in[4];
    const float* Wk   = (const float*)d_in[5];
    const float* bk   = (const float*)d_in[6];
    const float* Wv   = (const float*)d_in[7];
    const float* bv   = (const float*)d_in[8];
    const float* Wo   = (const float*)d_in[9];
    const float* bo   = (const float*)d_in[10];
    float* out = (float*)d_out;
    (void)in_sizes; (void)n_in; (void)out_size;

    // f32 -> f16 pre-conversion
    __half *dXc, *dXv, *dWq, *dWk, *dWv, *dWo;
    cudaGetSymbolAddress((void**)&dXc, g_Xch);
    cudaGetSymbolAddress((void**)&dXv, g_Xvh);
    cudaGetSymbolAddress((void**)&dWq, g_Wqh);
    cudaGetSymbolAddress((void**)&dWk, g_Wkh);
    cudaGetSymbolAddress((void**)&dWv, g_Wvh);
    cudaGetSymbolAddress((void**)&dWo, g_Woh);
    const int nX8 = MM*DD/8, nW8 = HH*DD*DKK/8, nWo8 = DD*DD/8;
    f2h_kernel<<<(nX8+255)/256, 256>>>(ctx, dXc, nX8);
    f2h_kernel<<<(nX8+255)/256, 256>>>(val, dXv, nX8);
    f2h_kernel<<<(nW8+255)/256, 256>>>(Wq, dWq, nW8);
    f2h_kernel<<<(nW8+255)/256, 256>>>(Wk, dWk, nW8);
    f2h_kernel<<<(nW8+255)/256, 256>>>(Wv, dWv, nW8);
    f2h_kernel<<<(nWo8+255)/256, 256>>>(Wo, dWo, nWo8);

    mask_bits_kernel<<<SS, 256>>>(mask);

    // projections
    int proj_smem = (2*128*64 + 2*64*64) * (int)sizeof(__half);  // 49152
    cudaFuncSetAttribute(projh_kernel<0>, cudaFuncAttributeMaxDynamicSharedMemorySize, proj_smem);
    cudaFuncSetAttribute(projh_kernel<1>, cudaFuncAttributeMaxDynamicSharedMemorySize, proj_smem);
    cudaFuncSetAttribute(projh_kernel<2>, cudaFuncAttributeMaxDynamicSharedMemorySize, proj_smem);
    dim3 pgrid(MM / 128, HH);
    projh_kernel<0><<<pgrid, 256, proj_smem>>>(bq);
    projh_kernel<1><<<pgrid, 256, proj_smem>>>(bk);
    projh_kernel<2><<<pgrid, 256, proj_smem>>>(bv);

    // attention
    dim3 agrid(SS / 128, BB * HH);
    attn_h_kernel<<<agrid, 256>>>();

    // output projection
    cudaFuncSetAttribute(outprojh_kernel, cudaFuncAttributeMaxDynamicSharedMemorySize, proj_smem);
    dim3 ogrid(DD / 64, MM / 128);
    outprojh_kernel<<<ogrid, 256, proj_smem>>>(bo, out);
}

// round 8
// speedup vs baseline: 3.5032x; 1.0073x over previous
#include <cuda_runtime.h>
#include <cuda_fp16.h>
#include <cstdint>
#include <math.h>

#define BB  4
#define SS  2048
#define DD  1024
#define HH  16
#define DKK 64
#define MM  (BB*SS)

// Static device scratch (half precision)
__device__ __half   g_Xch[(size_t)MM*DD];
__device__ __half   g_Xvh[(size_t)MM*DD];
__device__ __half   g_Wqh[(size_t)HH*DD*DKK];
__device__ __half   g_Wkh[(size_t)HH*DD*DKK];
__device__ __half   g_Wvh[(size_t)HH*DD*DKK];
__device__ __half   g_Woh[(size_t)DD*DD];
__device__ __half   g_Qh[(size_t)BB*HH*SS*DKK];
__device__ __half   g_Kh[(size_t)BB*HH*SS*DKK];
__device__ __half   g_Vh[(size_t)BB*HH*SS*DKK];
__device__ __half   g_AOh[(size_t)BB*SS*DD];
__device__ unsigned g_maskbits[SS * (SS/32)];

// ---------------------------------------------------------------------------
__device__ __forceinline__ float fexp2(float x) {
    float y;
    asm("ex2.approx.ftz.f32 %0, %1;" : "=f"(y) : "f"(x));
    return y;
}
__device__ __forceinline__ unsigned smem_u32(const void* p) {
    return (unsigned)__cvta_generic_to_shared(p);
}
__device__ __forceinline__ void ldsm4(unsigned& r0, unsigned& r1, unsigned& r2, unsigned& r3,
                                      unsigned addr) {
    asm volatile("ldmatrix.sync.aligned.m8n8.x4.shared.b16 {%0,%1,%2,%3}, [%4];"
                 : "=r"(r0), "=r"(r1), "=r"(r2), "=r"(r3) : "r"(addr));
}
__device__ __forceinline__ void ldsm4t(unsigned& r0, unsigned& r1, unsigned& r2, unsigned& r3,
                                       unsigned addr) {
    asm volatile("ldmatrix.sync.aligned.m8n8.x4.trans.shared.b16 {%0,%1,%2,%3}, [%4];"
                 : "=r"(r0), "=r"(r1), "=r"(r2), "=r"(r3) : "r"(addr));
}
__device__ __forceinline__ void mma16(float* c, unsigned a0, unsigned a1, unsigned a2, unsigned a3,
                                      unsigned b0, unsigned b1) {
    asm volatile(
        "mma.sync.aligned.m16n8k16.row.col.f32.f16.f16.f32 "
        "{%0,%1,%2,%3},{%4,%5,%6,%7},{%8,%9},{%0,%1,%2,%3};"
        : "+f"(c[0]), "+f"(c[1]), "+f"(c[2]), "+f"(c[3])
        : "r"(a0), "r"(a1), "r"(a2), "r"(a3), "r"(b0), "r"(b1));
}
__device__ __forceinline__ void cp16(unsigned dst, const void* src) {
    asm volatile("cp.async.cg.shared.global [%0], [%1], 16;" :: "r"(dst), "l"(src));
}
__device__ __forceinline__ void cp_commit() { asm volatile("cp.async.commit_group;"); }
__device__ __forceinline__ void cp_wait0()  { asm volatile("cp.async.wait_group 0;"); }
__device__ __forceinline__ void cp_wait1()  { asm volatile("cp.async.wait_group 1;"); }

// tile rows = 64 halfs (128B = 8 chunks of 16B). XOR swizzle
__device__ __forceinline__ unsigned tile_addr(unsigned base, int r, int c) {
    return base + (unsigned)(r*128 + (((c) ^ (r & 7)) << 4));
}
__device__ __forceinline__ unsigned h2u(__half2 h) {
    return *reinterpret_cast<unsigned*>(&h);
}

// ---------------------------------------------------------------------------
// One fused f32 -> f16 conversion over all six inputs (8 elems / thread)
// ---------------------------------------------------------------------------
#define NX8  (MM*DD/8)          // 1048576
#define NW8  (HH*DD*DKK/8)      // 131072
#define NWO8 (DD*DD/8)          // 131072
#define F2H_TOTAL (2*NX8 + 3*NW8 + NWO8)

__global__ void f2h_all_kernel(const float* __restrict__ ctx, const float* __restrict__ val,
                               const float* __restrict__ Wq, const float* __restrict__ Wk,
                               const float* __restrict__ Wv, const float* __restrict__ Wo)
{
    int i = blockIdx.x * blockDim.x + threadIdx.x;
    if (i >= F2H_TOTAL) return;
    const float* src; __half* dst; int o;
    if      (i < NX8)              { src = ctx; dst = g_Xch; o = i; }
    else if (i < 2*NX8)            { src = val; dst = g_Xvh; o = i - NX8; }
    else if (i < 2*NX8 + NW8)      { src = Wq;  dst = g_Wqh; o = i - 2*NX8; }
    else if (i < 2*NX8 + 2*NW8)    { src = Wk;  dst = g_Wkh; o = i - (2*NX8 + NW8); }
    else if (i < 2*NX8 + 3*NW8)    { src = Wv;  dst = g_Wvh; o = i - (2*NX8 + 2*NW8); }
    else                           { src = Wo;  dst = g_Woh; o = i - (2*NX8 + 3*NW8); }
    float4 v0 = *(const float4*)(src + (size_t)o*8);
    float4 v1 = *(const float4*)(src + (size_t)o*8 + 4);
    uint4 u;
    u.x = h2u(__floats2half2_rn(v0.x, v0.y));
    u.y = h2u(__floats2half2_rn(v0.z, v0.w));
    u.z = h2u(__floats2half2_rn(v1.x, v1.y));
    u.w = h2u(__floats2half2_rn(v1.z, v1.w));
    *(uint4*)(dst + (size_t)o*8) = u;
}

// ---------------------------------------------------------------------------
__global__ void mask_bits_kernel(const int* __restrict__ mask) {
    int row  = blockIdx.x;
    int warp = threadIdx.x >> 5;
    int lane = threadIdx.x & 31;
    for (int w = warp; w < SS/32; w += 8) {
        int m = mask[(size_t)row * SS + w*32 + lane];
        unsigned bits = __ballot_sync(0xffffffffu, m == 1);
        if (lane == 0) g_maskbits[row * (SS/32) + w] = bits;
    }
}

// ---------------------------------------------------------------------------
// Fused Q+K projection. BM=128, BN=64, BK=64 double-buffered.
// One X fragment set feeds both Wq and Wk mma streams.
// ---------------------------------------------------------------------------
__global__ __launch_bounds__(256)
void projqk_kernel(const float* __restrict__ bq, const float* __restrict__ bk)
{
    extern __shared__ __half sh[];
    __half* Xs  = sh;                   // 2 x 128x64
    __half* Wqs = sh + 2*128*64;        // 2 x 64x64
    __half* Wks = Wqs + 2*64*64;        // 2 x 64x64

    const int h    = blockIdx.y;
    const int row0 = blockIdx.x * 128;
    const int tid  = threadIdx.x;
    const int warp = tid >> 5;
    const int lane = tid & 31;
    const int wm   = warp >> 1;
    const int wn   = warp & 1;
    const int g    = lane >> 2;
    const int t    = lane & 3;

    const __half* Wqg = g_Wqh + (size_t)h * DD * DKK;
    const __half* Wkg = g_Wkh + (size_t)h * DD * DKK;
    const unsigned xs  = smem_u32(Xs);
    const unsigned wqs = smem_u32(Wqs);
    const unsigned wks = smem_u32(Wks);

    float accq[2][4][4], acck[2][4][4];
    #pragma unroll
    for (int mt = 0; mt < 2; mt++)
        #pragma unroll
        for (int nt = 0; nt < 4; nt++)
            #pragma unroll
            for (int i = 0; i < 4; i++) { accq[mt][nt][i] = 0.0f; acck[mt][nt][i] = 0.0f; }

    auto load_stage = [&](int kt, int buf) {
        unsigned xb  = xs  + buf*128*64*2;
        unsigned wqb = wqs + buf*64*64*2;
        unsigned wkb = wks + buf*64*64*2;
        #pragma unroll
        for (int i = 0; i < 4; i++) {
            int idx = tid + i*256;
            int r = idx >> 3, c = idx & 7;
            cp16(tile_addr(xb, r, c), g_Xch + (size_t)(row0 + r)*DD + kt + c*8);
        }
        #pragma unroll
        for (int i = 0; i < 2; i++) {
            int idx = tid + i*256;
            int r = idx >> 3, c = idx & 7;
            cp16(tile_addr(wqb, r, c), Wqg + (size_t)(kt + r)*DKK + c*8);
            cp16(tile_addr(wkb, r, c), Wkg + (size_t)(kt + r)*DKK + c*8);
        }
    };

    load_stage(0, 0);
    cp_commit();

    const int NS = DD / 64;
    for (int s = 0; s < NS; s++) {
        int buf = s & 1;
        if (s + 1 < NS) load_stage((s+1)*64, buf^1);
        cp_commit();
        cp_wait1();
        __syncthreads();

        unsigned xb  = xs  + buf*128*64*2;
        unsigned wqb = wqs + buf*64*64*2;
        unsigned wkb = wks + buf*64*64*2;

        #pragma unroll
        for (int j = 0; j < 4; j++) {
            unsigned af[2][4];
            #pragma unroll
            for (int mt = 0; mt < 2; mt++)
                ldsm4(af[mt][0], af[mt][1], af[mt][2], af[mt][3],
                      tile_addr(xb, wm*32 + mt*16 + (lane & 15), 2*j + (lane >> 4)));
            #pragma unroll
            for (int pp = 0; pp < 2; pp++) {
                int p = wn*2 + pp;
                unsigned b0, b1, b2, b3;
                ldsm4t(b0, b1, b2, b3,
                       tile_addr(wqb, 16*j + (lane & 7) + (lane & 8), 2*p + (lane >> 4)));
                #pragma unroll
                for (int mt = 0; mt < 2; mt++) {
                    mma16(accq[mt][pp*2],   af[mt][0], af[mt][1], af[mt][2], af[mt][3], b0, b1);
                    mma16(accq[mt][pp*2+1], af[mt][0], af[mt][1], af[mt][2], af[mt][3], b2, b3);
                }
                ldsm4t(b0, b1, b2, b3,
                       tile_addr(wkb, 16*j + (lane & 7) + (lane & 8), 2*p + (lane >> 4)));
                #pragma unroll
                for (int mt = 0; mt < 2; mt++) {
                    mma16(acck[mt][pp*2],   af[mt][0], af[mt][1], af[mt][2], af[mt][3], b0, b1);
                    mma16(acck[mt][pp*2+1], af[mt][0], af[mt][1], af[mt][2], af[mt][3], b2, b3);
                }
            }
        }
        __syncthreads();
    }

    #pragma unroll
    for (int nt = 0; nt < 4; nt++) {
        int col = wn*32 + nt*8 + 2*t;
        float bq0 = bq[h*DKK + col], bq1 = bq[h*DKK + col + 1];
        float bk0 = bk[h*DKK + col], bk1 = bk[h*DKK + col + 1];
        #pragma unroll
        for (int mt = 0; mt < 2; mt++) {
            #pragma unroll
            for (int half_ = 0; half_ < 2; half_++) {
                int grow = row0 + wm*32 + mt*16 + g + half_*8;
                int b = grow / SS, ss = grow % SS;
                size_t o = ((size_t)(b*HH + h)*SS + ss)*DKK + col;
                *(__half2*)(g_Qh + o) = __floats2half2_rn(accq[mt][nt][half_*2] + bq0,
                                                          accq[mt][nt][half_*2+1] + bq1);
                *(__half2*)(g_Kh + o) = __floats2half2_rn(acck[mt][nt][half_*2] + bk0,
                                                          acck[mt][nt][half_*2+1] + bk1);
            }
        }
    }
}

// ---------------------------------------------------------------------------
// V projection (single, unchanged structure from R7).
// ---------------------------------------------------------------------------
__global__ __launch_bounds__(256)
void projv_kernel(const float* __restrict__ bias)
{
    extern __shared__ __half sh[];
    __half* Xs = sh;                 // 2 x 128x64
    __half* Ws = sh + 2*128*64;      // 2 x 64x64

    const int h    = blockIdx.y;
    const int row0 = blockIdx.x * 128;
    const int tid  = threadIdx.x;
    const int warp = tid >> 5;
    const int lane = tid & 31;
    const int wm   = warp >> 1;
    const int wn   = warp & 1;
    const int g    = lane >> 2;
    const int t    = lane & 3;

    const __half* Wh = g_Wvh + (size_t)h * DD * DKK;
    const unsigned xs = smem_u32(Xs);
    const unsigned ws = smem_u32(Ws);

    float acc[2][4][4];
    #pragma unroll
    for (int mt = 0; mt < 2; mt++)
        #pragma unroll
        for (int nt = 0; nt < 4; nt++)
            #pragma unroll
            for (int i = 0; i < 4; i++) acc[mt][nt][i] = 0.0f;

    auto load_stage = [&](int kt, int buf) {
        unsigned xb = xs + buf*128*64*2;
        unsigned wb = ws + buf*64*64*2;
        #pragma unroll
        for (int i = 0; i < 4; i++) {
            int idx = tid + i*256;
            int r = idx >> 3, c = idx & 7;
            cp16(tile_addr(xb, r, c), g_Xvh + (size_t)(row0 + r)*DD + kt + c*8);
        }
        #pragma unroll
        for (int i = 0; i < 2; i++) {
            int idx = tid + i*256;
            int r = idx >> 3, c = idx & 7;
            cp16(tile_addr(wb, r, c), Wh + (size_t)(kt + r)*DKK + c*8);
        }
    };

    load_stage(0, 0);
    cp_commit();

    const int NS = DD / 64;
    for (int s = 0; s < NS; s++) {
        int buf = s & 1;
        if (s + 1 < NS) load_stage((s+1)*64, buf^1);
        cp_commit();
        cp_wait1();
        __syncthreads();

        unsigned xb = xs + buf*128*64*2;
        unsigned wb = ws + buf*64*64*2;

        #pragma unroll
        for (int j = 0; j < 4; j++) {
            unsigned af[2][4];
            #pragma unroll
            for (int mt = 0; mt < 2; mt++)
                ldsm4(af[mt][0], af[mt][1], af[mt][2], af[mt][3],
                      tile_addr(xb, wm*32 + mt*16 + (lane & 15), 2*j + (lane >> 4)));
            #pragma unroll
            for (int pp = 0; pp < 2; pp++) {
                int p = wn*2 + pp;
                unsigned b0, b1, b2, b3;
                ldsm4t(b0, b1, b2, b3,
                       tile_addr(wb, 16*j + (lane & 7) + (lane & 8), 2*p + (lane >> 4)));
                #pragma unroll
                for (int mt = 0; mt < 2; mt++) {
                    mma16(acc[mt][pp*2],   af[mt][0], af[mt][1], af[mt][2], af[mt][3], b0, b1);
                    mma16(acc[mt][pp*2+1], af[mt][0], af[mt][1], af[mt][2], af[mt][3], b2, b3);
                }
            }
        }
        __syncthreads();
    }

    #pragma unroll
    for (int nt = 0; nt < 4; nt++) {
        int col = wn*32 + nt*8 + 2*t;
        float bv0 = bias[h*DKK + col], bv1 = bias[h*DKK + col + 1];
        #pragma unroll
        for (int mt = 0; mt < 2; mt++) {
            #pragma unroll
            for (int half_ = 0; half_ < 2; half_++) {
                int grow = row0 + wm*32 + mt*16 + g + half_*8;
                int b = grow / SS, ss = grow % SS;
                size_t o = ((size_t)(b*HH + h)*SS + ss)*DKK + col;
                *(__half2*)(g_Vh + o) = __floats2half2_rn(acc[mt][nt][half_*2] + bv0,
                                                          acc[mt][nt][half_*2+1] + bv1);
            }
        }
    }
}

// ---------------------------------------------------------------------------
// Flash attention, BR=128, BC=64 (unchanged).
// ---------------------------------------------------------------------------
__global__ __launch_bounds__(256)
void attn_h_kernel()
{
    __shared__ __half Qs[128*64];
    __shared__ __half KVs[2][2][64*64];

    const int bh  = blockIdx.y;
    const int qr0 = blockIdx.x * 128;
    const int tid = threadIdx.x;
    const int wm  = tid >> 5;
    const int lane= tid & 31;
    const int g   = lane >> 2;
    const int t   = lane & 3;

    const __half* Qg = g_Qh + (size_t)bh * SS * DKK;
    const __half* Kg = g_Kh + (size_t)bh * SS * DKK;
    const __half* Vg = g_Vh + (size_t)bh * SS * DKK;

    const unsigned qs   = smem_u32(Qs);
    const unsigned kvs  = smem_u32(KVs);
    const int cr = tid >> 2, cc = tid & 3;

    #pragma unroll
    for (int i = 0; i < 4; i++) {
        int idx = tid + i*256;
        int r = idx >> 3, c = idx & 7;
        cp16(tile_addr(qs, r, c), Qg + (size_t)(qr0 + r)*DKK + c*8);
    }
    {
        unsigned kb = kvs, vb = kvs + 8192;
        cp16(tile_addr(kb, cr, cc),   Kg + (size_t)cr*DKK + cc*8);
        cp16(tile_addr(kb, cr, cc+4), Kg + (size_t)cr*DKK + (cc+4)*8);
        cp16(tile_addr(vb, cr, cc),   Vg + (size_t)cr*DKK + cc*8);
        cp16(tile_addr(vb, cr, cc+4), Vg + (size_t)cr*DKK + (cc+4)*8);
    }
    cp_commit();
    cp_wait0();
    __syncthreads();

    unsigned qf[4][4];
    {
        int m0 = wm*16;
        #pragma unroll
        for (int j = 0; j < 4; j++)
            ldsm4(qf[j][0], qf[j][1], qf[j][2], qf[j][3],
                  tile_addr(qs, m0 + (lane & 15), 2*j + (lane >> 4)));
    }

    float o[8][4];
    float m0_ = -1e30f, m1_ = -1e30f, l0 = 0.0f, l1 = 0.0f;
    #pragma unroll
    for (int nt = 0; nt < 8; nt++)
        #pragma unroll
        for (int i = 0; i < 4; i++) o[nt][i] = 0.0f;

    const int grow0 = qr0 + wm*16 + g;
    const int grow1 = grow0 + 8;
    const float SCL = 0.18033688011112042f;

    for (int it = 0; it < SS/64; it++) {
        int buf = it & 1;
        unsigned kb = kvs + buf*16384;
        unsigned vb = kb + 8192;

        if (it + 1 < SS/64) {
            const __half* Kn = Kg + (size_t)(it+1)*64*DKK;
            const __half* Vn = Vg + (size_t)(it+1)*64*DKK;
            unsigned kb2 = kvs + (buf^1)*16384, vb2 = kb2 + 8192;
            cp16(tile_addr(kb2, cr, cc),   Kn + (size_t)cr*DKK + cc*8);
            cp16(tile_addr(kb2, cr, cc+4), Kn + (size_t)cr*DKK + (cc+4)*8);
            cp16(tile_addr(vb2, cr, cc),   Vn + (size_t)cr*DKK + cc*8);
            cp16(tile_addr(vb2, cr, cc+4), Vn + (size_t)cr*DKK + (cc+4)*8);
        }
        cp_commit();
        cp_wait1();
        __syncthreads();

        float s[8][4];
        #pragma unroll
        for (int nt = 0; nt < 8; nt++)
            #pragma unroll
            for (int i = 0; i < 4; i++) s[nt][i] = 0.0f;

        #pragma unroll
        for (int j = 0; j < 4; j++) {
            #pragma unroll
            for (int p = 0; p < 4; p++) {
                unsigned b0, b1, b2, b3;
                ldsm4(b0, b1, b2, b3,
                      tile_addr(kb, p*16 + (lane & 7) + ((lane & 16) >> 1),
                                2*j + ((lane >> 3) & 1)));
                mma16(s[2*p],   qf[j][0], qf[j][1], qf[j][2], qf[j][3], b0, b1);
                mma16(s[2*p+1], qf[j][0], qf[j][1], qf[j][2], qf[j][3], b2, b3);
            }
        }

        int kw = it*2;
        unsigned w0a = g_maskbits[grow0*(SS/32) + kw];
        unsigned w0b = g_maskbits[grow0*(SS/32) + kw + 1];
        unsigned w1a = g_maskbits[grow1*(SS/32) + kw];
        unsigned w1b = g_maskbits[grow1*(SS/32) + kw + 1];
        #pragma unroll
        for (int nt = 0; nt < 8; nt++) {
            int c = nt*8 + 2*t;
            unsigned wr0 = (c < 32) ? w0a : w0b;
            unsigned wr1 = (c < 32) ? w1a : w1b;
            int sh_ = c & 31;
            s[nt][0] = ((wr0 >> sh_)     & 1u) ? -1e9f : s[nt][0]*SCL;
            s[nt][1] = ((wr0 >> (sh_+1)) & 1u) ? -1e9f : s[nt][1]*SCL;
            s[nt][2] = ((wr1 >> sh_)     & 1u) ? -1e9f : s[nt][2]*SCL;
            s[nt][3] = ((wr1 >> (sh_+1)) & 1u) ? -1e9f : s[nt][3]*SCL;
        }

        float mx0 = -1e30f, mx1 = -1e30f;
        #pragma unroll
        for (int nt = 0; nt < 8; nt++) {
            mx0 = fmaxf(mx0, fmaxf(s[nt][0], s[nt][1]));
            mx1 = fmaxf(mx1, fmaxf(s[nt][2], s[nt][3]));
        }
        mx0 = fmaxf(mx0, __shfl_xor_sync(0xffffffffu, mx0, 1));
        mx0 = fmaxf(mx0, __shfl_xor_sync(0xffffffffu, mx0, 2));
        mx1 = fmaxf(mx1, __shfl_xor_sync(0xffffffffu, mx1, 1));
        mx1 = fmaxf(mx1, __shfl_xor_sync(0xffffffffu, mx1, 2));
        float mn0 = fmaxf(m0_, mx0);
        float mn1 = fmaxf(m1_, mx1);
        float sum0 = 0.0f, sum1 = 0.0f;
        #pragma unroll
        for (int nt = 0; nt < 8; nt++) {
            s[nt][0] = fexp2(s[nt][0] - mn0); sum0 += s[nt][0];
            s[nt][1] = fexp2(s[nt][1] - mn0); sum0 += s[nt][1];
            s[nt][2] = fexp2(s[nt][2] - mn1); sum1 += s[nt][2];
            s[nt][3] = fexp2(s[nt][3] - mn1); sum1 += s[nt][3];
        }
        sum0 += __shfl_xor_sync(0xffffffffu, sum0, 1);
        sum0 += __shfl_xor_sync(0xffffffffu, sum0, 2);
        sum1 += __shfl_xor_sync(0xffffffffu, sum1, 1);
        sum1 += __shfl_xor_sync(0xffffffffu, sum1, 2);
        float sc0 = fexp2(m0_ - mn0);
        float sc1 = fexp2(m1_ - mn1);
        l0 = l0*sc0 + sum0;  m0_ = mn0;
        l1 = l1*sc1 + sum1;  m1_ = mn1;
        #pragma unroll
        for (int nt = 0; nt < 8; nt++) {
            o[nt][0] *= sc0; o[nt][1] *= sc0;
            o[nt][2] *= sc1; o[nt][3] *= sc1;
        }

        unsigned pf[4][4];
        #pragma unroll
        for (int j = 0; j < 4; j++) {
            pf[j][0] = h2u(__floats2half2_rn(s[2*j][0],   s[2*j][1]));
            pf[j][1] = h2u(__floats2half2_rn(s[2*j][2],   s[2*j][3]));
            pf[j][2] = h2u(__floats2half2_rn(s[2*j+1][0], s[2*j+1][1]));
            pf[j][3] = h2u(__floats2half2_rn(s[2*j+1][2], s[2*j+1][3]));
        }

        #pragma unroll
        for (int j = 0; j < 4; j++) {
            #pragma unroll
            for (int p = 0; p < 4; p++) {
                unsigned b0, b1, b2, b3;
                ldsm4t(b0, b1, b2, b3,
                       tile_addr(vb, 16*j + (lane & 7) + (lane & 8), 2*p + (lane >> 4)));
                mma16(o[2*p],   pf[j][0], pf[j][1], pf[j][2], pf[j][3], b0, b1);
                mma16(o[2*p+1], pf[j][0], pf[j][1], pf[j][2], pf[j][3], b2, b3);
            }
        }
        __syncthreads();
    }

    const int b = bh >> 4, h = bh & 15;
    float inv0 = 1.0f / l0, inv1 = 1.0f / l1;
    #pragma unroll
    for (int nt = 0; nt < 8; nt++) {
        int c = nt*8 + 2*t;
        size_t base0 = ((size_t)(b*SS + grow0))*DD + h*DKK + c;
        size_t base1 = ((size_t)(b*SS + grow1))*DD + h*DKK + c;
        *(__half2*)(g_AOh + base0) = __floats2half2_rn(o[nt][0]*inv0, o[nt][1]*inv0);
        *(__half2*)(g_AOh + base1) = __floats2half2_rn(o[nt][2]*inv1, o[nt][3]*inv1);
    }
}

// ---------------------------------------------------------------------------
// Output projection (unchanged). BM=128, BN=64, BK=64.
// ---------------------------------------------------------------------------
__global__ __launch_bounds__(256)
void outprojh_kernel(const float* __restrict__ bo,
                     float* __restrict__ out)
{
    extern __shared__ __half sh[];
    __half* As = sh;
    __half* Ws = sh + 2*128*64;

    const int n0   = blockIdx.x * 64;
    const int row0 = blockIdx.y * 128;
    const int tid  = threadIdx.x;
    const int warp = tid >> 5;
    const int lane = tid & 31;
    const int wm   = warp >> 1;
    const int wn   = warp & 1;
    const int g    = lane >> 2;
    const int t    = lane & 3;

    const unsigned as_ = smem_u32(As);
    const unsigned ws_ = smem_u32(Ws);

    float acc[2][4][4];
    #pragma unroll
    for (int mt = 0; mt < 2; mt++)
        #pragma unroll
        for (int nt = 0; nt < 4; nt++)
            #pragma unroll
            for (int i = 0; i < 4; i++) acc[mt][nt][i] = 0.0f;

    auto load_stage = [&](int kt, int buf) {
        unsigned ab = as_ + buf*128*64*2;
        unsigned wb = ws_ + buf*64*64*2;
        #pragma unroll
        for (int i = 0; i < 4; i++) {
            int idx = tid + i*256;
            int r = idx >> 3, c = idx & 7;
            cp16(tile_addr(ab, r, c), g_AOh + (size_t)(row0 + r)*DD + kt + c*8);
        }
        #pragma unroll
        for (int i = 0; i < 2; i++) {
            int idx = tid + i*256;
            int r = idx >> 3, c = idx & 7;
            cp16(tile_addr(wb, r, c), g_Woh + (size_t)(n0 + r)*DD + kt + c*8);
        }
    };

    load_stage(0, 0);
    cp_commit();

    const int NS = DD / 64;
    for (int s = 0; s < NS; s++) {
        int buf = s & 1;
        if (s + 1 < NS) load_stage((s+1)*64, buf^1);
        cp_commit();
        cp_wait1();
        __syncthreads();

        unsigned ab = as_ + buf*128*64*2;
        unsigned wb = ws_ + buf*64*64*2;

        #pragma unroll
        for (int j = 0; j < 4; j++) {
            unsigned af[2][4];
            #pragma unroll
            for (int mt = 0; mt < 2; mt++)
                ldsm4(af[mt][0], af[mt][1], af[mt][2], af[mt][3],
                      tile_addr(ab, wm*32 + mt*16 + (lane & 15), 2*j + (lane >> 4)));
            #pragma unroll
            for (int pp = 0; pp < 2; pp++) {
                int p = wn*2 + pp;
                unsigned b0, b1, b2, b3;
                ldsm4(b0, b1, b2, b3,
                      tile_addr(wb, p*16 + (lane & 7) + ((lane & 16) >> 1),
                                2*j + ((lane >> 3) & 1)));
                #pragma unroll
                for (int mt = 0; mt < 2; mt++) {
                    mma16(acc[mt][pp*2],   af[mt][0], af[mt][1], af[mt][2], af[mt][3], b0, b1);
                    mma16(acc[mt][pp*2+1], af[mt][0], af[mt][1], af[mt][2], af[mt][3], b2, b3);
                }
            }
        }
        __syncthreads();
    }

    #pragma unroll
    for (int nt = 0; nt < 4; nt++) {
        int col = n0 + wn*32 + nt*8 + 2*t;
        float bv0 = bo[col], bv1 = bo[col+1];
        #pragma unroll
        for (int mt = 0; mt < 2; mt++) {
            #pragma unroll
            for (int half_ = 0; half_ < 2; half_++) {
                size_t grow = row0 + wm*32 + mt*16 + g + half_*8;
                float2 v;
                v.x = acc[mt][nt][half_*2+0] + bv0;
                v.y = acc[mt][nt][half_*2+1] + bv1;
                *(float2*)(out + grow*DD + col) = v;
            }
        }
    }
}

// ---------------------------------------------------------------------------
extern "C" void kernel_launch(void* const* d_in, const int* in_sizes, int n_in,
                              void* d_out, int out_size)
{
    const float* ctx  = (const float*)d_in[0];
    const float* val  = (const float*)d_in[1];
    const int*   mask = (const int*)  d_in[2];
    const float* Wq   = (const float*)d_in[3];
    const float* bq   = (const float*)d_in[4];
    const float* Wk   = (const float*)d_in[5];
    const float* bk   = (const float*)d_in[6];
    const float* Wv   = (const float*)d_in[7];
    const float* bv   = (const float*)d_in[8];
    const float* Wo   = (const float*)d_in[9];
    const float* bo   = (const float*)d_in[10];
    float* out = (float*)d_out;
    (void)in_sizes; (void)n_in; (void)out_size;

    // fused f32 -> f16 conversion
    f2h_all_kernel<<<(F2H_TOTAL + 255)/256, 256>>>(ctx, val, Wq, Wk, Wv, Wo);
    mask_bits_kernel<<<SS, 256>>>(mask);

    // projections
    int qk_smem = (2*128*64 + 4*64*64) * (int)sizeof(__half);   // 65536
    int v_smem  = (2*128*64 + 2*64*64) * (int)sizeof(__half);   // 49152
    cudaFuncSetAttribute(projqk_kernel, cudaFuncAttributeMaxDynamicSharedMemorySize, qk_smem);
    cudaFuncSetAttribute(projv_kernel,  cudaFuncAttributeMaxDynamicSharedMemorySize, v_smem);
    dim3 pgrid(MM / 128, HH);
    projqk_kernel<<<pgrid, 256, qk_smem>>>(bq, bk);
    projv_kernel<<<pgrid, 256, v_smem>>>(bv);

    // attention
    dim3 agrid(SS / 128, BB * HH);
    attn_h_kernel<<<agrid, 256>>>();

    // output projection
    cudaFuncSetAttribute(outprojh_kernel, cudaFuncAttributeMaxDynamicSharedMemorySize, v_smem);
    dim3 ogrid(DD / 64, MM / 128);
    outprojh_kernel<<<ogrid, 256, v_smem>>>(bo, out);
}